// round 4
// baseline (speedup 1.0000x reference)
#include <cuda_runtime.h>
#include <cstdint>

#define NROWS 32768   // B*T
#define DDIM  512
#define HDIM  512
#define MCODES 1024

// ---------------- scratch (static device allocations; no cudaMalloc) -------
__device__ unsigned long long g_best[NROWS];
__device__ float g_counts[MCODES];
__device__ float g_dw[MCODES * DDIM];
__device__ float g_esq[MCODES];
__device__ float g_xsq[NROWS];
__device__ float g_vqrow[NROWS];
__device__ float g_newc[MCODES];
__device__ int   g_mask_mode;
__device__ int   g_lab_mode;     // 0 = int32, 1 = int64
__device__ float g_a1[(size_t)NROWS * DDIM];
__device__ float g_h[(size_t)NROWS * HDIM];
__device__ float g_a2[(size_t)NROWS * HDIM];
__device__ float g_logits[(size_t)NROWS * MCODES];

// ---------------- reduction helpers ----------------------------------------
__device__ __forceinline__ float warpReduceSum(float v) {
#pragma unroll
    for (int o = 16; o > 0; o >>= 1) v += __shfl_down_sync(0xffffffffu, v, o);
    return v;
}
__device__ __forceinline__ float warpReduceMax(float v) {
#pragma unroll
    for (int o = 16; o > 0; o >>= 1) v = fmaxf(v, __shfl_down_sync(0xffffffffu, v, o));
    return v;
}

__device__ __forceinline__ float blockReduceSum(float v) {
    __shared__ float s[32];
    __syncthreads();                 // protect reuse across sequential calls
    v = warpReduceSum(v);
    int lane = threadIdx.x & 31, w = threadIdx.x >> 5;
    if (lane == 0) s[w] = v;
    __syncthreads();
    int nw = blockDim.x >> 5;
    float r = (threadIdx.x < nw) ? s[threadIdx.x] : 0.f;
    if (w == 0) {
        r = warpReduceSum(r);
        if (lane == 0) s[0] = r;
    }
    __syncthreads();
    return s[0];
}

__device__ __forceinline__ float blockReduceMax(float v) {
    __shared__ float s[32];
    __syncthreads();
    v = warpReduceMax(v);
    int lane = threadIdx.x & 31, w = threadIdx.x >> 5;
    if (lane == 0) s[w] = v;
    __syncthreads();
    int nw = blockDim.x >> 5;
    float r = (threadIdx.x < nw) ? s[threadIdx.x] : __int_as_float(0xff800000);
    if (w == 0) {
        r = warpReduceMax(r);
        if (lane == 0) s[0] = r;
    }
    __syncthreads();
    return s[0];
}

__device__ __forceinline__ unsigned fkey(float f) {
    unsigned u = __float_as_uint(f);
    return (u & 0x80000000u) ? ~u : (u | 0x80000000u);
}

// ---------------- init ------------------------------------------------------
__global__ void init_kernel() {
    int i = blockIdx.x * blockDim.x + threadIdx.x;   // grid covers 524288
    if (i < NROWS)  g_best[i]   = ~0ull;
    if (i < MCODES) g_counts[i] = 0.f;
    g_dw[i] = 0.f;
}

// Strict sequential fp32 sum of squares per row (matches jnp.sum(x**2, -1)
// with XLA-CPU in-order reduction): s = fl(s + fl(x_i * x_i)).
__global__ void seqsq_kernel(const float* __restrict__ X, float* __restrict__ out) {
    __shared__ float row[DDIM];
    const float4* src = (const float4*)(X + (size_t)blockIdx.x * DDIM);
    ((float4*)row)[threadIdx.x] = src[threadIdx.x];   // 128 threads * 4 = 512
    __syncthreads();
    if (threadIdx.x == 0) {
        float s = 0.f;
#pragma unroll 8
        for (int i = 0; i < DDIM; i++)
            s = __fadd_rn(s, __fmul_rn(row[i], row[i]));
        out[blockIdx.x] = s;
    }
}

// ---------------- SGEMM: 128x128 tile, 8x8 per thread, BK=8 ----------------
// C[N,Mc] = A[N,K] @ B   where B is [K,Mc] row-major (BT=false)
//                        or    B is [Mc,K] row-major (BT=true, i.e. A@B^T)
// ARGMIN: compute d = fl( fl(xsq[n] + esq[m]) - 2*acc ), replicating the
// reference's large-scale rounding, and track (min d, min col) per row.
template <bool BT, bool ARGMIN>
__global__ void __launch_bounds__(256) sgemm_kernel(
    const float* __restrict__ A, const float* __restrict__ B,
    float* __restrict__ C, int K, int ldb)
{
    __shared__ float As[8][128];
    __shared__ float Bs[8][128];

    const int tid = threadIdx.x;
    const int tx = tid & 15, ty = tid >> 4;
    const int rowBase = blockIdx.y * 128;
    const int colBase = blockIdx.x * 128;

    float acc[8][8];
#pragma unroll
    for (int i = 0; i < 8; i++)
#pragma unroll
        for (int j = 0; j < 8; j++) acc[i][j] = 0.f;

    const int a_r = tid >> 1;          // 0..127
    const int a_c = (tid & 1) * 4;     // 0 or 4
    const int b_r = tid >> 5;          // 0..7
    const int b_c = (tid & 31) * 4;    // 0..124

    const float* Aptr = A + (size_t)(rowBase + a_r) * K + a_c;

    for (int k0 = 0; k0 < K; k0 += 8) {
        float4 av = *(const float4*)(Aptr + k0);
        As[a_c + 0][a_r] = av.x;
        As[a_c + 1][a_r] = av.y;
        As[a_c + 2][a_r] = av.z;
        As[a_c + 3][a_r] = av.w;
        if (BT) {
            float4 bv = *(const float4*)(B + (size_t)(colBase + a_r) * K + k0 + a_c);
            Bs[a_c + 0][a_r] = bv.x;
            Bs[a_c + 1][a_r] = bv.y;
            Bs[a_c + 2][a_r] = bv.z;
            Bs[a_c + 3][a_r] = bv.w;
        } else {
            *(float4*)&Bs[b_r][b_c] =
                *(const float4*)(B + (size_t)(k0 + b_r) * ldb + colBase + b_c);
        }
        __syncthreads();
#pragma unroll
        for (int kk = 0; kk < 8; kk++) {
            float ra[8], rb[8];
            *(float4*)(ra)     = *(const float4*)&As[kk][ty * 8];
            *(float4*)(ra + 4) = *(const float4*)&As[kk][ty * 8 + 4];
            *(float4*)(rb)     = *(const float4*)&Bs[kk][tx * 8];
            *(float4*)(rb + 4) = *(const float4*)&Bs[kk][tx * 8 + 4];
#pragma unroll
            for (int i = 0; i < 8; i++)
#pragma unroll
                for (int j = 0; j < 8; j++)
                    acc[i][j] = fmaf(ra[i], rb[j], acc[i][j]);
        }
        __syncthreads();
    }

    if (!ARGMIN) {
#pragma unroll
        for (int i = 0; i < 8; i++) {
            float* crow = C + (size_t)(rowBase + ty * 8 + i) * ldb + colBase + tx * 8;
            *(float4*)(crow)     = make_float4(acc[i][0], acc[i][1], acc[i][2], acc[i][3]);
            *(float4*)(crow + 4) = make_float4(acc[i][4], acc[i][5], acc[i][6], acc[i][7]);
        }
    } else {
        __shared__ unsigned long long rowmin[128];
        if (tid < 128) rowmin[tid] = ~0ull;
        __syncthreads();
#pragma unroll
        for (int i = 0; i < 8; i++) {
            float xs = g_xsq[rowBase + ty * 8 + i];
            float bd = __int_as_float(0x7f800000);
            int bc = 0;
#pragma unroll
            for (int j = 0; j < 8; j++) {
                int col = colBase + tx * 8 + j;
                // replicate reference rounding: (esq + xsq) - 2*c, all fp32 steps
                float t1 = __fadd_rn(g_esq[col], xs);
                float d  = __fadd_rn(t1, -2.0f * acc[i][j]);  // 2*acc exact
                if (d < bd) { bd = d; bc = col; }
            }
            unsigned long long key = ((unsigned long long)fkey(bd) << 32) | (unsigned)bc;
            atomicMin(&rowmin[ty * 8 + i], key);
        }
        __syncthreads();
        if (tid < 128) atomicMin(&g_best[rowBase + tid], rowmin[tid]);
    }
}

// ---------------- post-VQ: gather, quantized_st, vq loss, counts, dw -------
__global__ void postvq_kernel(const float* __restrict__ x,
                              const float* __restrict__ emb,
                              float* __restrict__ out_q)
{
    int row = blockIdx.x;
    int idx = (int)(unsigned)(g_best[row] & 0xFFFFFFFFull);
    const float4* xr = (const float4*)(x   + (size_t)row * DDIM);
    const float4* er = (const float4*)(emb + (size_t)idx * DDIM);
    float4 xv = xr[threadIdx.x];
    float4 ev = er[threadIdx.x];
    // quantized_st = x + (q - x)  (replicate reference arithmetic)
    float4 q;
    q.x = xv.x + (ev.x - xv.x);
    q.y = xv.y + (ev.y - xv.y);
    q.z = xv.z + (ev.z - xv.z);
    q.w = xv.w + (ev.w - xv.w);
    ((float4*)(out_q + (size_t)row * DDIM))[threadIdx.x] = q;

    float dx = xv.x - ev.x, dy = xv.y - ev.y, dz = xv.z - ev.z, dw2 = xv.w - ev.w;
    float s = dx * dx + dy * dy + dz * dz + dw2 * dw2;

    float* dwp = g_dw + (size_t)idx * DDIM + threadIdx.x * 4;
    atomicAdd(dwp + 0, xv.x);
    atomicAdd(dwp + 1, xv.y);
    atomicAdd(dwp + 2, xv.z);
    atomicAdd(dwp + 3, xv.w);

    s = blockReduceSum(s);
    if (threadIdx.x == 0) {
        g_vqrow[row] = 0.25f * s;   // COMMIT * sum_d (x-q)^2
        atomicAdd(&g_counts[idx], 1.0f);
    }
}

// ---------------- EMA count + perplexity (single block, 1024 threads) ------
__global__ void ema_kernel(const float* __restrict__ ema_count,
                           float* __restrict__ out_cnt,
                           float* __restrict__ out_perp)
{
    int m = threadIdx.x;
    float c = g_counts[m];
    float nc0 = 0.999f * ema_count[m] + 0.001f * c;
    float n = blockReduceSum(nc0);
    float newc = (nc0 + 1e-5f) / (n + (float)MCODES * 1e-5f) * n;
    out_cnt[m] = newc;
    g_newc[m] = newc;
    float p = c * (1.0f / (float)NROWS);
    float t = p * logf(p + 1e-10f);
    float s = blockReduceSum(t);
    if (m == 0) out_perp[0] = expf(-s);
}

__global__ void embw_kernel(const float* __restrict__ ema_weight,
                            float* __restrict__ out_emb,
                            float* __restrict__ out_w)
{
    int i = blockIdx.x * 256 + threadIdx.x;   // grid covers MCODES*DDIM
    float w = 0.999f * ema_weight[i] + 0.001f * g_dw[i];
    out_w[i] = w;
    out_emb[i] = w / g_newc[i >> 9];
}

// ---------------- LayerNorm + ReLU ------------------------------------------
template <int W>
__global__ void ln_relu_kernel(const float* __restrict__ X,
                               const float* __restrict__ g,
                               const float* __restrict__ b,
                               float* __restrict__ Y)
{
    constexpr int PER = W / 256;
    int row = blockIdx.x;
    const float* x = X + (size_t)row * W;
    float v[PER];
    float s = 0.f;
#pragma unroll
    for (int i = 0; i < PER; i++) { v[i] = x[threadIdx.x + i * 256]; s += v[i]; }
    float mean = blockReduceSum(s) * (1.0f / W);
    float s2 = 0.f;
#pragma unroll
    for (int i = 0; i < PER; i++) { float d = v[i] - mean; s2 += d * d; }
    float var = blockReduceSum(s2) * (1.0f / W);
    float rstd = rsqrtf(var + 1e-5f);
#pragma unroll
    for (int i = 0; i < PER; i++) {
        int c = threadIdx.x + i * 256;
        float o = (v[i] - mean) * rstd * g[c] + b[c];
        Y[(size_t)row * W + c] = fmaxf(o, 0.f);
    }
}

// ---------------- dtype detection (deterministic from input) ----------------
// mask: mode 0: 32-bit words {0,1} (int32 bool); mode 1: float32 {0,1};
//       mode 2: packed bytes (uint8/bool)
__global__ void detect_mask_kernel(const unsigned* __restrict__ m) {
    __shared__ int bad, gt1;
    if (threadIdx.x == 0) { bad = 0; gt1 = 0; }
    __syncthreads();
    for (int i = threadIdx.x; i < 8192; i += blockDim.x) {
        unsigned v = m[i];
        if (v > 1u) {
            atomicOr(&gt1, 1);
            if (v != 0x3F800000u) atomicOr(&bad, 1);
        }
    }
    __syncthreads();
    if (threadIdx.x == 0) g_mask_mode = (gt1 == 0) ? 0 : (bad ? 2 : 1);
}

// labels: int64 iff ALL odd 32-bit words are zero (labels in [0,1024), so an
// int64 buffer has all-zero high words; an int32 buffer of random labels has
// nonzero odd-indexed entries with probability ~1).
__global__ void detect_lab_kernel(const unsigned* __restrict__ lab) {
    __shared__ int any_nz;
    if (threadIdx.x == 0) any_nz = 0;
    __syncthreads();
    for (int i = threadIdx.x; i < NROWS / 2; i += blockDim.x) {
        if (lab[2 * i + 1] != 0u) atomicOr(&any_nz, 1);
    }
    __syncthreads();
    if (threadIdx.x == 0) g_lab_mode = any_nz ? 0 : 1;
}

// ---------------- cross-entropy + final loss --------------------------------
__global__ void ce_kernel(const void* __restrict__ labels,
                          const void* __restrict__ mask,
                          float* __restrict__ out_loss)
{
    int row = blockIdx.x;
    const float* lg = g_logits + (size_t)row * MCODES;
    float v[4];
#pragma unroll
    for (int i = 0; i < 4; i++) v[i] = lg[threadIdx.x + i * 256];
    float mx = fmaxf(fmaxf(v[0], v[1]), fmaxf(v[2], v[3]));
    mx = blockReduceMax(mx);
    float s = 0.f;
#pragma unroll
    for (int i = 0; i < 4; i++) s += expf(v[i] - mx);
    s = blockReduceSum(s);
    if (threadIdx.x == 0) {
        float lse = mx + logf(s);
        int lab = g_lab_mode ? (int)((const long long*)labels)[row]
                             : ((const int*)labels)[row];
        int mode = g_mask_mode;
        bool invalid;
        if (mode == 2)      invalid = ((const unsigned char*)mask)[row] != 0;
        else if (mode == 1) invalid = ((const float*)mask)[row] != 0.f;
        else                invalid = ((const int*)mask)[row] != 0;
        float ce = invalid ? 0.f : (lse - lg[lab]);
        out_loss[row] = ce + g_vqrow[row];
    }
}

// ---------------- launch -----------------------------------------------------
extern "C" void kernel_launch(void* const* d_in, const int* in_sizes, int n_in,
                              void* d_out, int out_size)
{
    const float* x         = (const float*)d_in[0];
    const void*  mask      = d_in[1];
    const void*  labels    = d_in[2];
    const float* emb       = (const float*)d_in[3];
    const float* ema_count = (const float*)d_in[4];
    const float* ema_wt    = (const float*)d_in[5];
    const float* ln1g      = (const float*)d_in[6];
    const float* ln1b      = (const float*)d_in[7];
    const float* W1        = (const float*)d_in[8];
    const float* ln2g      = (const float*)d_in[9];
    const float* ln2b      = (const float*)d_in[10];
    const float* W2        = (const float*)d_in[11];

    float* out      = (float*)d_out;
    float* out_q    = out;                                    // [N, D]
    float* out_loss = out + (size_t)NROWS * DDIM;             // [N]
    float* out_perp = out_loss + NROWS;                       // [1]
    float* out_emb  = out_perp + 1;                           // [M, D]
    float* out_cnt  = out_emb + (size_t)MCODES * DDIM;        // [M]
    float* out_w    = out_cnt + MCODES;                       // [M, D]

    void *pa1, *ph, *pa2, *plog, *pxsq, *pesq;
    cudaGetSymbolAddress(&pa1, g_a1);
    cudaGetSymbolAddress(&ph, g_h);
    cudaGetSymbolAddress(&pa2, g_a2);
    cudaGetSymbolAddress(&plog, g_logits);
    cudaGetSymbolAddress(&pxsq, g_xsq);
    cudaGetSymbolAddress(&pesq, g_esq);

    // --- VQ path ---
    init_kernel<<<2048, 256>>>();
    seqsq_kernel<<<MCODES, 128>>>(emb, (float*)pesq);
    seqsq_kernel<<<NROWS, 128>>>(x, (float*)pxsq);
    sgemm_kernel<true, true><<<dim3(8, 256), 256>>>(x, emb, nullptr, DDIM, MCODES);
    postvq_kernel<<<NROWS, 128>>>(x, emb, out_q);
    ema_kernel<<<1, 1024>>>(ema_count, out_cnt, out_perp);
    embw_kernel<<<2048, 256>>>(ema_wt, out_emb, out_w);

    // --- decoder path: h = relu(LN(x)) @ W1 [512x512], logits = relu(LN(h)) @ W2 [512x1024]
    ln_relu_kernel<512><<<NROWS, 256>>>(x, ln1g, ln1b, (float*)pa1);
    sgemm_kernel<false, false><<<dim3(HDIM / 128, 256), 256>>>((const float*)pa1, W1, (float*)ph, DDIM, HDIM);
    ln_relu_kernel<512><<<NROWS, 256>>>((const float*)ph, ln2g, ln2b, (float*)pa2);
    sgemm_kernel<false, false><<<dim3(MCODES / 128, 256), 256>>>((const float*)pa2, W2, (float*)plog, HDIM, MCODES);

    // --- loss ---
    detect_mask_kernel<<<1, 256>>>((const unsigned*)mask);
    detect_lab_kernel<<<1, 256>>>((const unsigned*)labels);
    ce_kernel<<<NROWS, 256>>>(labels, mask, out_loss);
}

// round 6
// speedup vs baseline: 1.7183x; 1.7183x over previous
#include <cuda_runtime.h>
#include <cuda_bf16.h>
#include <cstdint>

#define NROWS 32768   // B*T
#define DDIM  512
#define HDIM  512
#define MCODES 1024

// ---------------- scratch (static device allocations; no cudaMalloc) -------
__device__ unsigned long long g_best[NROWS];
__device__ float g_counts[MCODES];
__device__ float g_dw[MCODES * DDIM];
__device__ float g_esq[MCODES];
__device__ float g_xsq[NROWS];
__device__ float g_vqrow[NROWS];
__device__ float g_newc[MCODES];
__device__ int   g_mask_mode;
__device__ int   g_lab_mode;     // 0 = int32, 1 = int64
__device__ __nv_bfloat16 g_a1b[(size_t)NROWS * DDIM];
__device__ __nv_bfloat16 g_a2b[(size_t)NROWS * HDIM];
__device__ __nv_bfloat16 g_w1t[(size_t)HDIM * DDIM];     // [N=512, K=512]
__device__ __nv_bfloat16 g_w2t[(size_t)MCODES * HDIM];   // [N=1024, K=512]
__device__ float g_h[(size_t)NROWS * HDIM];
__device__ float g_logits[(size_t)NROWS * MCODES];

// ---------------- reduction helpers ----------------------------------------
__device__ __forceinline__ float warpReduceSum(float v) {
#pragma unroll
    for (int o = 16; o > 0; o >>= 1) v += __shfl_down_sync(0xffffffffu, v, o);
    return v;
}
__device__ __forceinline__ float warpReduceMax(float v) {
#pragma unroll
    for (int o = 16; o > 0; o >>= 1) v = fmaxf(v, __shfl_down_sync(0xffffffffu, v, o));
    return v;
}
__device__ __forceinline__ float blockReduceSum(float v) {
    __shared__ float s[32];
    __syncthreads();
    v = warpReduceSum(v);
    int lane = threadIdx.x & 31, w = threadIdx.x >> 5;
    if (lane == 0) s[w] = v;
    __syncthreads();
    int nw = blockDim.x >> 5;
    float r = (threadIdx.x < nw) ? s[threadIdx.x] : 0.f;
    if (w == 0) { r = warpReduceSum(r); if (lane == 0) s[0] = r; }
    __syncthreads();
    return s[0];
}
__device__ __forceinline__ float blockReduceMax(float v) {
    __shared__ float s[32];
    __syncthreads();
    v = warpReduceMax(v);
    int lane = threadIdx.x & 31, w = threadIdx.x >> 5;
    if (lane == 0) s[w] = v;
    __syncthreads();
    int nw = blockDim.x >> 5;
    float r = (threadIdx.x < nw) ? s[threadIdx.x] : __int_as_float(0xff800000);
    if (w == 0) { r = warpReduceMax(r); if (lane == 0) s[0] = r; }
    __syncthreads();
    return s[0];
}
__device__ __forceinline__ unsigned fkey(float f) {
    unsigned u = __float_as_uint(f);
    return (u & 0x80000000u) ? ~u : (u | 0x80000000u);
}
__device__ __forceinline__ uint32_t smem_addr_u32(const void* p) {
    return (uint32_t)__cvta_generic_to_shared(p);
}

// ---------------- init ------------------------------------------------------
__global__ void init_kernel() {
    int i = blockIdx.x * blockDim.x + threadIdx.x;   // grid covers 524288
    if (i < NROWS)  g_best[i]   = ~0ull;
    if (i < MCODES) g_counts[i] = 0.f;
    g_dw[i] = 0.f;
}

// Strict sequential fp32 sum of squares per row (reference rounding order).
__global__ void seqsq_kernel(const float* __restrict__ X, float* __restrict__ out) {
    __shared__ float row[DDIM];
    const float4* src = (const float4*)(X + (size_t)blockIdx.x * DDIM);
    ((float4*)row)[threadIdx.x] = src[threadIdx.x];
    __syncthreads();
    if (threadIdx.x == 0) {
        float s = 0.f;
#pragma unroll 8
        for (int i = 0; i < DDIM; i++)
            s = __fadd_rn(s, __fmul_rn(row[i], row[i]));
        out[blockIdx.x] = s;
    }
}

// ---------------- fp32 SGEMM with bit-exact argmin epilogue -----------------
__global__ void __launch_bounds__(256) argmin_gemm_kernel(
    const float* __restrict__ A, const float* __restrict__ B, int K)
{
    __shared__ float As[8][128];
    __shared__ float Bs[8][128];

    const int tid = threadIdx.x;
    const int tx = tid & 15, ty = tid >> 4;
    const int rowBase = blockIdx.y * 128;
    const int colBase = blockIdx.x * 128;

    float acc[8][8];
#pragma unroll
    for (int i = 0; i < 8; i++)
#pragma unroll
        for (int j = 0; j < 8; j++) acc[i][j] = 0.f;

    const int a_r = tid >> 1;
    const int a_c = (tid & 1) * 4;
    const float* Aptr = A + (size_t)(rowBase + a_r) * K + a_c;

    for (int k0 = 0; k0 < K; k0 += 8) {
        float4 av = *(const float4*)(Aptr + k0);
        As[a_c + 0][a_r] = av.x;
        As[a_c + 1][a_r] = av.y;
        As[a_c + 2][a_r] = av.z;
        As[a_c + 3][a_r] = av.w;
        float4 bv = *(const float4*)(B + (size_t)(colBase + a_r) * K + k0 + a_c);
        Bs[a_c + 0][a_r] = bv.x;
        Bs[a_c + 1][a_r] = bv.y;
        Bs[a_c + 2][a_r] = bv.z;
        Bs[a_c + 3][a_r] = bv.w;
        __syncthreads();
#pragma unroll
        for (int kk = 0; kk < 8; kk++) {
            float ra[8], rb[8];
            *(float4*)(ra)     = *(const float4*)&As[kk][ty * 8];
            *(float4*)(ra + 4) = *(const float4*)&As[kk][ty * 8 + 4];
            *(float4*)(rb)     = *(const float4*)&Bs[kk][tx * 8];
            *(float4*)(rb + 4) = *(const float4*)&Bs[kk][tx * 8 + 4];
#pragma unroll
            for (int i = 0; i < 8; i++)
#pragma unroll
                for (int j = 0; j < 8; j++)
                    acc[i][j] = fmaf(ra[i], rb[j], acc[i][j]);
        }
        __syncthreads();
    }

    __shared__ unsigned long long rowmin[128];
    if (tid < 128) rowmin[tid] = ~0ull;
    __syncthreads();
#pragma unroll
    for (int i = 0; i < 8; i++) {
        float xs = g_xsq[rowBase + ty * 8 + i];
        float bd = __int_as_float(0x7f800000);
        int bc = 0;
#pragma unroll
        for (int j = 0; j < 8; j++) {
            int col = colBase + tx * 8 + j;
            float t1 = __fadd_rn(g_esq[col], xs);
            float d  = __fadd_rn(t1, -2.0f * acc[i][j]);
            if (d < bd) { bd = d; bc = col; }
        }
        unsigned long long key = ((unsigned long long)fkey(bd) << 32) | (unsigned)bc;
        atomicMin(&rowmin[ty * 8 + i], key);
    }
    __syncthreads();
    if (tid < 128) atomicMin(&g_best[rowBase + tid], rowmin[tid]);
}

// ---------------- bf16 tensor-core GEMM (mma.sync m16n8k16) ----------------
// C[M,N] = A[M,512] @ Bt[N,512]^T.  CTA tile 128x128, 8 warps (2M x 4N),
// warp tile 64x32 = 4x4 m16n8 tiles, BK=32.
// smem rows padded to 80B so 8-row ldmatrix groups are bank-conflict-free.
#define TC_LDA 80   // bytes per smem row (32 bf16 data + 8 pad)

__device__ __forceinline__ void mma16816(float* d, const uint32_t* a,
                                         const uint32_t* b, const float* c) {
    asm volatile(
        "mma.sync.aligned.m16n8k16.row.col.f32.bf16.bf16.f32 "
        "{%0,%1,%2,%3}, {%4,%5,%6,%7}, {%8,%9}, {%10,%11,%12,%13};"
        : "=f"(d[0]), "=f"(d[1]), "=f"(d[2]), "=f"(d[3])
        : "r"(a[0]), "r"(a[1]), "r"(a[2]), "r"(a[3]),
          "r"(b[0]), "r"(b[1]),
          "f"(c[0]), "f"(c[1]), "f"(c[2]), "f"(c[3]));
}

__global__ void __launch_bounds__(256) tcgemm_kernel(
    const __nv_bfloat16* __restrict__ A,   // [Mtot, 512] row-major bf16
    const __nv_bfloat16* __restrict__ Bt,  // [Ntot, 512] row-major bf16
    float* __restrict__ C, int ldc)
{
    __shared__ __align__(16) unsigned char sA[128 * TC_LDA];
    __shared__ __align__(16) unsigned char sB[128 * TC_LDA];

    const int tid = threadIdx.x;
    const int lane = tid & 31, wid = tid >> 5;
    const int warp_m = wid & 1;           // 0..1 (64 rows each)
    const int warp_n = wid >> 1;          // 0..3 (32 cols each)
    const int rowBase = blockIdx.y * 128;
    const int colBase = blockIdx.x * 128;

    float acc[4][4][4];
#pragma unroll
    for (int i = 0; i < 4; i++)
#pragma unroll
        for (int j = 0; j < 4; j++)
#pragma unroll
            for (int r = 0; r < 4; r++) acc[i][j][r] = 0.f;

    // ldmatrix source addresses (fixed per thread; k-offset added per step)
    const uint32_t sAu = smem_addr_u32(sA);
    const uint32_t sBu = smem_addr_u32(sB);
    // A: row = warp_m*64 + mt*16 + lane%16 ; col8 = (lane/16)*8
    const uint32_t aAddrBase = sAu + (uint32_t)(warp_m * 64 + (lane & 15)) * TC_LDA
                             + (uint32_t)(lane >> 4) * 16;
    // B: row = warp_n*32 + nt*8 + lane%8 ; col8 = ((lane>>3)&1)*8  (lanes 16+ mirror)
    const uint32_t bAddrBase = sBu + (uint32_t)(warp_n * 32 + (lane & 7)) * TC_LDA
                             + (uint32_t)((lane >> 3) & 1) * 16;

    for (int k0 = 0; k0 < 512; k0 += 32) {
        // load tiles: 128 rows x 64B each, 512 x 16B chunks, 2 per thread
#pragma unroll
        for (int it = 0; it < 2; it++) {
            int idx = tid + it * 256;
            int r = idx >> 2, c = idx & 3;
            uint4 va = *(const uint4*)(A + (size_t)(rowBase + r) * 512 + k0 + c * 8);
            *(uint4*)(sA + r * TC_LDA + c * 16) = va;
            uint4 vb = *(const uint4*)(Bt + (size_t)(colBase + r) * 512 + k0 + c * 8);
            *(uint4*)(sB + r * TC_LDA + c * 16) = vb;
        }
        __syncthreads();

#pragma unroll
        for (int ks = 0; ks < 2; ks++) {      // two k16 steps
            uint32_t afr[4][4];
#pragma unroll
            for (int mt = 0; mt < 4; mt++) {
                uint32_t addr = aAddrBase + (uint32_t)mt * 16 * TC_LDA + ks * 32;
                asm volatile("ldmatrix.sync.aligned.m8n8.x4.shared.b16 {%0,%1,%2,%3}, [%4];"
                             : "=r"(afr[mt][0]), "=r"(afr[mt][1]),
                               "=r"(afr[mt][2]), "=r"(afr[mt][3]) : "r"(addr));
            }
            uint32_t bfr[4][2];
#pragma unroll
            for (int nt = 0; nt < 4; nt++) {
                uint32_t addr = bAddrBase + (uint32_t)nt * 8 * TC_LDA + ks * 32;
                asm volatile("ldmatrix.sync.aligned.m8n8.x2.shared.b16 {%0,%1}, [%2];"
                             : "=r"(bfr[nt][0]), "=r"(bfr[nt][1]) : "r"(addr));
            }
#pragma unroll
            for (int mt = 0; mt < 4; mt++)
#pragma unroll
                for (int nt = 0; nt < 4; nt++)
                    mma16816(acc[mt][nt], afr[mt], bfr[nt], acc[mt][nt]);
        }
        __syncthreads();
    }

    // epilogue: direct float2 stores
#pragma unroll
    for (int mt = 0; mt < 4; mt++) {
#pragma unroll
        for (int nt = 0; nt < 4; nt++) {
            int row0 = rowBase + warp_m * 64 + mt * 16 + (lane >> 2);
            int col  = colBase + warp_n * 32 + nt * 8 + (lane & 3) * 2;
            *(float2*)(C + (size_t)row0 * ldc + col) =
                make_float2(acc[mt][nt][0], acc[mt][nt][1]);
            *(float2*)(C + (size_t)(row0 + 8) * ldc + col) =
                make_float2(acc[mt][nt][2], acc[mt][nt][3]);
        }
    }
}

// ---------------- weight transpose + bf16 convert ---------------------------
// W: [512, N] fp32 row-major  ->  Wt: [N, 512] bf16 row-major
__global__ void wconv_kernel(const float* __restrict__ W,
                             __nv_bfloat16* __restrict__ Wt, int N)
{
    __shared__ float tile[32][33];
    int k0 = blockIdx.y * 32, n0 = blockIdx.x * 32;
    int tx = threadIdx.x & 31, ty = threadIdx.x >> 5;   // 8 rows
#pragma unroll
    for (int i = 0; i < 32; i += 8)
        tile[ty + i][tx] = W[(size_t)(k0 + ty + i) * N + n0 + tx];
    __syncthreads();
#pragma unroll
    for (int i = 0; i < 32; i += 8)
        Wt[(size_t)(n0 + ty + i) * 512 + k0 + tx] = __float2bfloat16(tile[tx][ty + i]);
}

// ---------------- post-VQ: gather, quantized_st, vq loss, counts, dw -------
__global__ void postvq_kernel(const float* __restrict__ x,
                              const float* __restrict__ emb,
                              float* __restrict__ out_q)
{
    int row = blockIdx.x;
    int idx = (int)(unsigned)(g_best[row] & 0xFFFFFFFFull);
    const float4* xr = (const float4*)(x   + (size_t)row * DDIM);
    const float4* er = (const float4*)(emb + (size_t)idx * DDIM);
    float4 xv = xr[threadIdx.x];
    float4 ev = er[threadIdx.x];
    float4 q;
    q.x = xv.x + (ev.x - xv.x);
    q.y = xv.y + (ev.y - xv.y);
    q.z = xv.z + (ev.z - xv.z);
    q.w = xv.w + (ev.w - xv.w);
    ((float4*)(out_q + (size_t)row * DDIM))[threadIdx.x] = q;

    float dx = xv.x - ev.x, dy = xv.y - ev.y, dz = xv.z - ev.z, dw2 = xv.w - ev.w;
    float s = dx * dx + dy * dy + dz * dz + dw2 * dw2;

    float* dwp = g_dw + (size_t)idx * DDIM + threadIdx.x * 4;
    atomicAdd(dwp + 0, xv.x);
    atomicAdd(dwp + 1, xv.y);
    atomicAdd(dwp + 2, xv.z);
    atomicAdd(dwp + 3, xv.w);

    s = blockReduceSum(s);
    if (threadIdx.x == 0) {
        g_vqrow[row] = 0.25f * s;
        atomicAdd(&g_counts[idx], 1.0f);
    }
}

// ---------------- EMA count + perplexity ------------------------------------
__global__ void ema_kernel(const float* __restrict__ ema_count,
                           float* __restrict__ out_cnt,
                           float* __restrict__ out_perp)
{
    int m = threadIdx.x;
    float c = g_counts[m];
    float nc0 = 0.999f * ema_count[m] + 0.001f * c;
    float n = blockReduceSum(nc0);
    float newc = (nc0 + 1e-5f) / (n + (float)MCODES * 1e-5f) * n;
    out_cnt[m] = newc;
    g_newc[m] = newc;
    float p = c * (1.0f / (float)NROWS);
    float t = p * logf(p + 1e-10f);
    float s = blockReduceSum(t);
    if (m == 0) out_perp[0] = expf(-s);
}

__global__ void embw_kernel(const float* __restrict__ ema_weight,
                            float* __restrict__ out_emb,
                            float* __restrict__ out_w)
{
    int i = blockIdx.x * 256 + threadIdx.x;
    float w = 0.999f * ema_weight[i] + 0.001f * g_dw[i];
    out_w[i] = w;
    out_emb[i] = w / g_newc[i >> 9];
}

// ---------------- LayerNorm + ReLU -> bf16 ----------------------------------
__global__ void ln_relu_bf16_kernel(const float* __restrict__ X,
                                    const float* __restrict__ g,
                                    const float* __restrict__ b,
                                    __nv_bfloat16* __restrict__ Y)
{
    constexpr int W = 512;
    constexpr int PER = 2;
    int row = blockIdx.x;
    const float* x = X + (size_t)row * W;
    float v[PER];
    float s = 0.f;
#pragma unroll
    for (int i = 0; i < PER; i++) { v[i] = x[threadIdx.x + i * 256]; s += v[i]; }
    float mean = blockReduceSum(s) * (1.0f / W);
    float s2 = 0.f;
#pragma unroll
    for (int i = 0; i < PER; i++) { float d = v[i] - mean; s2 += d * d; }
    float var = blockReduceSum(s2) * (1.0f / W);
    float rstd = rsqrtf(var + 1e-5f);
#pragma unroll
    for (int i = 0; i < PER; i++) {
        int c = threadIdx.x + i * 256;
        float o = (v[i] - mean) * rstd * g[c] + b[c];
        Y[(size_t)row * W + c] = __float2bfloat16(fmaxf(o, 0.f));
    }
}

// ---------------- dtype detection -------------------------------------------
__global__ void detect_mask_kernel(const unsigned* __restrict__ m) {
    __shared__ int bad, gt1;
    if (threadIdx.x == 0) { bad = 0; gt1 = 0; }
    __syncthreads();
    for (int i = threadIdx.x; i < 8192; i += blockDim.x) {
        unsigned v = m[i];
        if (v > 1u) {
            atomicOr(&gt1, 1);
            if (v != 0x3F800000u) atomicOr(&bad, 1);
        }
    }
    __syncthreads();
    if (threadIdx.x == 0) g_mask_mode = (gt1 == 0) ? 0 : (bad ? 2 : 1);
}

__global__ void detect_lab_kernel(const unsigned* __restrict__ lab) {
    __shared__ int any_nz;
    if (threadIdx.x == 0) any_nz = 0;
    __syncthreads();
    for (int i = threadIdx.x; i < NROWS / 2; i += blockDim.x) {
        if (lab[2 * i + 1] != 0u) atomicOr(&any_nz, 1);
    }
    __syncthreads();
    if (threadIdx.x == 0) g_lab_mode = any_nz ? 0 : 1;
}

// ---------------- cross-entropy + final loss --------------------------------
__global__ void ce_kernel(const void* __restrict__ labels,
                          const void* __restrict__ mask,
                          float* __restrict__ out_loss)
{
    int row = blockIdx.x;
    const float* lg = g_logits + (size_t)row * MCODES;
    float v[4];
#pragma unroll
    for (int i = 0; i < 4; i++) v[i] = lg[threadIdx.x + i * 256];
    float mx = fmaxf(fmaxf(v[0], v[1]), fmaxf(v[2], v[3]));
    mx = blockReduceMax(mx);
    float s = 0.f;
#pragma unroll
    for (int i = 0; i < 4; i++) s += expf(v[i] - mx);
    s = blockReduceSum(s);
    if (threadIdx.x == 0) {
        float lse = mx + logf(s);
        int lab = g_lab_mode ? (int)((const long long*)labels)[row]
                             : ((const int*)labels)[row];
        int mode = g_mask_mode;
        bool invalid;
        if (mode == 2)      invalid = ((const unsigned char*)mask)[row] != 0;
        else if (mode == 1) invalid = ((const float*)mask)[row] != 0.f;
        else                invalid = ((const int*)mask)[row] != 0;
        float ce = invalid ? 0.f : (lse - lg[lab]);
        out_loss[row] = ce + g_vqrow[row];
    }
}

// ---------------- launch -----------------------------------------------------
extern "C" void kernel_launch(void* const* d_in, const int* in_sizes, int n_in,
                              void* d_out, int out_size)
{
    const float* x         = (const float*)d_in[0];
    const void*  mask      = d_in[1];
    const void*  labels    = d_in[2];
    const float* emb       = (const float*)d_in[3];
    const float* ema_count = (const float*)d_in[4];
    const float* ema_wt    = (const float*)d_in[5];
    const float* ln1g      = (const float*)d_in[6];
    const float* ln1b      = (const float*)d_in[7];
    const float* W1        = (const float*)d_in[8];
    const float* ln2g      = (const float*)d_in[9];
    const float* ln2b      = (const float*)d_in[10];
    const float* W2        = (const float*)d_in[11];

    float* out      = (float*)d_out;
    float* out_q    = out;
    float* out_loss = out + (size_t)NROWS * DDIM;
    float* out_perp = out_loss + NROWS;
    float* out_emb  = out_perp + 1;
    float* out_cnt  = out_emb + (size_t)MCODES * DDIM;
    float* out_w    = out_cnt + MCODES;

    void *pa1, *ph, *pa2, *pxsq, *pesq, *pw1t, *pw2t, *plog;
    cudaGetSymbolAddress(&pa1, g_a1b);
    cudaGetSymbolAddress(&ph, g_h);
    cudaGetSymbolAddress(&pa2, g_a2b);
    cudaGetSymbolAddress(&pxsq, g_xsq);
    cudaGetSymbolAddress(&pesq, g_esq);
    cudaGetSymbolAddress(&pw1t, g_w1t);
    cudaGetSymbolAddress(&pw2t, g_w2t);
    cudaGetSymbolAddress(&plog, g_logits);

    // --- VQ path (bit-exact fp32) ---
    init_kernel<<<2048, 256>>>();
    seqsq_kernel<<<MCODES, 128>>>(emb, (float*)pesq);
    seqsq_kernel<<<NROWS, 128>>>(x, (float*)pxsq);
    argmin_gemm_kernel<<<dim3(8, 256), 256>>>(x, emb, DDIM);
    postvq_kernel<<<NROWS, 128>>>(x, emb, out_q);
    ema_kernel<<<1, 1024>>>(ema_count, out_cnt, out_perp);
    embw_kernel<<<2048, 256>>>(ema_wt, out_emb, out_w);

    // --- decoder path: bf16 tensor-core GEMMs (mma.sync) ---
    wconv_kernel<<<dim3(HDIM / 32, DDIM / 32), 256>>>(W1, (__nv_bfloat16*)pw1t, HDIM);
    wconv_kernel<<<dim3(MCODES / 32, HDIM / 32), 256>>>(W2, (__nv_bfloat16*)pw2t, MCODES);
    ln_relu_bf16_kernel<<<NROWS, 256>>>(x, ln1g, ln1b, (__nv_bfloat16*)pa1);
    tcgemm_kernel<<<dim3(HDIM / 128, 256), 256>>>((const __nv_bfloat16*)pa1,
                                                  (const __nv_bfloat16*)pw1t,
                                                  (float*)ph, HDIM);
    ln_relu_bf16_kernel<<<NROWS, 256>>>((const float*)ph, ln2g, ln2b, (__nv_bfloat16*)pa2);
    tcgemm_kernel<<<dim3(MCODES / 128, 256), 256>>>((const __nv_bfloat16*)pa2,
                                                    (const __nv_bfloat16*)pw2t,
                                                    (float*)plog, MCODES);

    // --- loss ---
    detect_mask_kernel<<<1, 256>>>((const unsigned*)mask);
    detect_lab_kernel<<<1, 256>>>((const unsigned*)labels);
    ce_kernel<<<NROWS, 256>>>(labels, mask, out_loss);
}

// round 7
// speedup vs baseline: 1.7433x; 1.0146x over previous
#include <cuda_runtime.h>
#include <cuda_bf16.h>
#include <cstdint>

#define NROWS 32768   // B*T
#define DDIM  512
#define HDIM  512
#define MCODES 1024

// ---------------- scratch (static device allocations; no cudaMalloc) -------
__device__ unsigned long long g_best[NROWS];
__device__ float g_counts[MCODES];
__device__ float g_dw[MCODES * DDIM];
__device__ float g_esq[MCODES];
__device__ float g_xsq[NROWS];
__device__ float g_vqrow[NROWS];
__device__ float g_newc[MCODES];
__device__ int   g_mask_mode;
__device__ int   g_lab_mode;     // 0 = int32, 1 = int64
__device__ __nv_bfloat16 g_xs[(size_t)NROWS * 1536];    // x 3-way bf16 split
__device__ __nv_bfloat16 g_es[(size_t)MCODES * 1536];   // emb 3-way bf16 split
__device__ __nv_bfloat16 g_a1b[(size_t)NROWS * DDIM];
__device__ __nv_bfloat16 g_a2b[(size_t)NROWS * HDIM];
__device__ __nv_bfloat16 g_w1t[(size_t)HDIM * DDIM];     // [N=512, K=512]
__device__ __nv_bfloat16 g_w2t[(size_t)MCODES * HDIM];   // [N=1024, K=512]
__device__ float g_h[(size_t)NROWS * HDIM];
__device__ float g_logits[(size_t)NROWS * MCODES];

// ---------------- reduction helpers ----------------------------------------
__device__ __forceinline__ float warpReduceSum(float v) {
#pragma unroll
    for (int o = 16; o > 0; o >>= 1) v += __shfl_down_sync(0xffffffffu, v, o);
    return v;
}
__device__ __forceinline__ float warpReduceMax(float v) {
#pragma unroll
    for (int o = 16; o > 0; o >>= 1) v = fmaxf(v, __shfl_down_sync(0xffffffffu, v, o));
    return v;
}
__device__ __forceinline__ float blockReduceSum(float v) {
    __shared__ float s[32];
    __syncthreads();
    v = warpReduceSum(v);
    int lane = threadIdx.x & 31, w = threadIdx.x >> 5;
    if (lane == 0) s[w] = v;
    __syncthreads();
    int nw = blockDim.x >> 5;
    float r = (threadIdx.x < nw) ? s[threadIdx.x] : 0.f;
    if (w == 0) { r = warpReduceSum(r); if (lane == 0) s[0] = r; }
    __syncthreads();
    return s[0];
}
__device__ __forceinline__ float blockReduceMax(float v) {
    __shared__ float s[32];
    __syncthreads();
    v = warpReduceMax(v);
    int lane = threadIdx.x & 31, w = threadIdx.x >> 5;
    if (lane == 0) s[w] = v;
    __syncthreads();
    int nw = blockDim.x >> 5;
    float r = (threadIdx.x < nw) ? s[threadIdx.x] : __int_as_float(0xff800000);
    if (w == 0) { r = warpReduceMax(r); if (lane == 0) s[0] = r; }
    __syncthreads();
    return s[0];
}
__device__ __forceinline__ unsigned fkey(float f) {
    unsigned u = __float_as_uint(f);
    return (u & 0x80000000u) ? ~u : (u | 0x80000000u);
}
__device__ __forceinline__ uint32_t smem_addr_u32(const void* p) {
    return (uint32_t)__cvta_generic_to_shared(p);
}

// ---------------- init ------------------------------------------------------
__global__ void init_kernel() {
    int i = blockIdx.x * blockDim.x + threadIdx.x;   // grid covers 524288
    if (i < NROWS)  g_best[i]   = ~0ull;
    if (i < MCODES) g_counts[i] = 0.f;
    g_dw[i] = 0.f;
}

// Strict sequential fp32 sum of squares per row (reference rounding order).
__global__ void seqsq_kernel(const float* __restrict__ X, float* __restrict__ out) {
    __shared__ float row[DDIM];
    const float4* src = (const float4*)(X + (size_t)blockIdx.x * DDIM);
    ((float4*)row)[threadIdx.x] = src[threadIdx.x];
    __syncthreads();
    if (threadIdx.x == 0) {
        float s = 0.f;
#pragma unroll 8
        for (int i = 0; i < DDIM; i++)
            s = __fadd_rn(s, __fmul_rn(row[i], row[i]));
        out[blockIdx.x] = s;
    }
}

// 3-way bf16 split: v = v0 + v1 + v2 (+ ~2^-27 residual)
__global__ void split3_kernel(const float* __restrict__ V,
                              __nv_bfloat16* __restrict__ S, int nrows)
{
    int i = blockIdx.x * 256 + threadIdx.x;          // over nrows*512
    int row = i >> 9, col = i & 511;
    float v = V[i];
    __nv_bfloat16 h0 = __float2bfloat16(v);
    float r1 = v - __bfloat162float(h0);
    __nv_bfloat16 h1 = __float2bfloat16(r1);
    float r2 = r1 - __bfloat162float(h1);
    __nv_bfloat16 h2 = __float2bfloat16(r2);
    size_t base = (size_t)row * 1536 + col;
    S[base]        = h0;
    S[base + 512]  = h1;
    S[base + 1024] = h2;
}

// ---------------- mma.sync helpers ------------------------------------------
__device__ __forceinline__ void mma16816(float* d, const uint32_t* a,
                                         const uint32_t* b, const float* c) {
    asm volatile(
        "mma.sync.aligned.m16n8k16.row.col.f32.bf16.bf16.f32 "
        "{%0,%1,%2,%3}, {%4,%5,%6,%7}, {%8,%9}, {%10,%11,%12,%13};"
        : "=f"(d[0]), "=f"(d[1]), "=f"(d[2]), "=f"(d[3])
        : "r"(a[0]), "r"(a[1]), "r"(a[2]), "r"(a[3]),
          "r"(b[0]), "r"(b[1]),
          "f"(c[0]), "f"(c[1]), "f"(c[2]), "f"(c[3]));
}

#define TC_LDA 80   // bytes per smem row (32 bf16 data + 8 pad)

// ---------------- tensor-core argmin GEMM -----------------------------------
// acc[n,m] = x·e via 6-term 3-way-bf16 split (fp32-equivalent products).
// Epilogue: d = fl(fl(esq+xsq) - 2*acc), bucket-exact argmin w/ low-index ties.
__global__ void __launch_bounds__(256) argmin_tc_kernel(
    const __nv_bfloat16* __restrict__ A,   // g_xs [NROWS, 1536]
    const __nv_bfloat16* __restrict__ B)   // g_es [MCODES, 1536]
{
    __shared__ __align__(16) unsigned char sA[128 * TC_LDA];
    __shared__ __align__(16) unsigned char sB[128 * TC_LDA];

    const int tid = threadIdx.x;
    const int lane = tid & 31, wid = tid >> 5;
    const int warp_m = wid & 1;
    const int warp_n = wid >> 1;
    const int rowBase = blockIdx.y * 128;
    const int colBase = blockIdx.x * 128;

    float acc[4][4][4];
#pragma unroll
    for (int i = 0; i < 4; i++)
#pragma unroll
        for (int j = 0; j < 4; j++)
#pragma unroll
            for (int r = 0; r < 4; r++) acc[i][j][r] = 0.f;

    const uint32_t sAu = smem_addr_u32(sA);
    const uint32_t sBu = smem_addr_u32(sB);
    const uint32_t aAddrBase = sAu + (uint32_t)(warp_m * 64 + (lane & 15)) * TC_LDA
                             + (uint32_t)(lane >> 4) * 16;
    const uint32_t bAddrBase = sBu + (uint32_t)(warp_n * 32 + (lane & 7)) * TC_LDA
                             + (uint32_t)((lane >> 3) & 1) * 16;

    // product terms with magnitude >= 2^-18: (x0,e0),(x0,e1),(x1,e0),(x0,e2),(x1,e1),(x2,e0)
    const int segA[6] = {0, 0, 512, 0, 512, 1024};
    const int segB[6] = {0, 512, 0, 1024, 512, 0};

#pragma unroll 1
    for (int s = 0; s < 6; s++) {
        const __nv_bfloat16* Aseg = A + segA[s];
        const __nv_bfloat16* Bseg = B + segB[s];
#pragma unroll 1
        for (int k0 = 0; k0 < 512; k0 += 32) {
#pragma unroll
            for (int it = 0; it < 2; it++) {
                int idx = tid + it * 256;
                int r = idx >> 2, c = idx & 3;
                uint4 va = *(const uint4*)(Aseg + (size_t)(rowBase + r) * 1536 + k0 + c * 8);
                *(uint4*)(sA + r * TC_LDA + c * 16) = va;
                uint4 vb = *(const uint4*)(Bseg + (size_t)(colBase + r) * 1536 + k0 + c * 8);
                *(uint4*)(sB + r * TC_LDA + c * 16) = vb;
            }
            __syncthreads();
#pragma unroll
            for (int ks = 0; ks < 2; ks++) {
                uint32_t afr[4][4];
#pragma unroll
                for (int mt = 0; mt < 4; mt++) {
                    uint32_t addr = aAddrBase + (uint32_t)mt * 16 * TC_LDA + ks * 32;
                    asm volatile("ldmatrix.sync.aligned.m8n8.x4.shared.b16 {%0,%1,%2,%3}, [%4];"
                                 : "=r"(afr[mt][0]), "=r"(afr[mt][1]),
                                   "=r"(afr[mt][2]), "=r"(afr[mt][3]) : "r"(addr));
                }
                uint32_t bfr[4][2];
#pragma unroll
                for (int nt = 0; nt < 4; nt++) {
                    uint32_t addr = bAddrBase + (uint32_t)nt * 8 * TC_LDA + ks * 32;
                    asm volatile("ldmatrix.sync.aligned.m8n8.x2.shared.b16 {%0,%1}, [%2];"
                                 : "=r"(bfr[nt][0]), "=r"(bfr[nt][1]) : "r"(addr));
                }
#pragma unroll
                for (int mt = 0; mt < 4; mt++)
#pragma unroll
                    for (int nt = 0; nt < 4; nt++)
                        mma16816(acc[mt][nt], afr[mt], bfr[nt], acc[mt][nt]);
            }
            __syncthreads();
        }
    }

    // ---- argmin epilogue (bucket rounding identical to reference) ----
    __shared__ unsigned long long rowmin[128];
    if (tid < 128) rowmin[tid] = ~0ull;
    __syncthreads();

    const int r_in8 = lane >> 2;
#pragma unroll
    for (int mt = 0; mt < 4; mt++) {
#pragma unroll
        for (int half = 0; half < 2; half++) {
            int row = warp_m * 64 + mt * 16 + r_in8 + half * 8;
            float xs = g_xsq[rowBase + row];
            float bd = __int_as_float(0x7f800000);
            int bc = 0;
#pragma unroll
            for (int nt = 0; nt < 4; nt++) {
#pragma unroll
                for (int c = 0; c < 2; c++) {
                    int col = colBase + warp_n * 32 + nt * 8 + (lane & 3) * 2 + c;
                    float a = acc[mt][nt][half * 2 + c];
                    float t1 = __fadd_rn(g_esq[col], xs);
                    float d  = __fadd_rn(t1, -2.0f * a);
                    if (d < bd) { bd = d; bc = col; }
                }
            }
            unsigned long long key = ((unsigned long long)fkey(bd) << 32) | (unsigned)bc;
            unsigned long long o1 = __shfl_xor_sync(0xffffffffu, key, 1);
            if (o1 < key) key = o1;
            unsigned long long o2 = __shfl_xor_sync(0xffffffffu, key, 2);
            if (o2 < key) key = o2;
            if ((lane & 3) == 0) atomicMin(&rowmin[row], key);
        }
    }
    __syncthreads();
    if (tid < 128) atomicMin(&g_best[rowBase + tid], rowmin[tid]);
}

// ---------------- bf16 tensor-core GEMM (decoder) ---------------------------
__global__ void __launch_bounds__(256) tcgemm_kernel(
    const __nv_bfloat16* __restrict__ A,   // [Mtot, 512] row-major bf16
    const __nv_bfloat16* __restrict__ Bt,  // [Ntot, 512] row-major bf16
    float* __restrict__ C, int ldc)
{
    __shared__ __align__(16) unsigned char sA[128 * TC_LDA];
    __shared__ __align__(16) unsigned char sB[128 * TC_LDA];

    const int tid = threadIdx.x;
    const int lane = tid & 31, wid = tid >> 5;
    const int warp_m = wid & 1;
    const int warp_n = wid >> 1;
    const int rowBase = blockIdx.y * 128;
    const int colBase = blockIdx.x * 128;

    float acc[4][4][4];
#pragma unroll
    for (int i = 0; i < 4; i++)
#pragma unroll
        for (int j = 0; j < 4; j++)
#pragma unroll
            for (int r = 0; r < 4; r++) acc[i][j][r] = 0.f;

    const uint32_t sAu = smem_addr_u32(sA);
    const uint32_t sBu = smem_addr_u32(sB);
    const uint32_t aAddrBase = sAu + (uint32_t)(warp_m * 64 + (lane & 15)) * TC_LDA
                             + (uint32_t)(lane >> 4) * 16;
    const uint32_t bAddrBase = sBu + (uint32_t)(warp_n * 32 + (lane & 7)) * TC_LDA
                             + (uint32_t)((lane >> 3) & 1) * 16;

    for (int k0 = 0; k0 < 512; k0 += 32) {
#pragma unroll
        for (int it = 0; it < 2; it++) {
            int idx = tid + it * 256;
            int r = idx >> 2, c = idx & 3;
            uint4 va = *(const uint4*)(A + (size_t)(rowBase + r) * 512 + k0 + c * 8);
            *(uint4*)(sA + r * TC_LDA + c * 16) = va;
            uint4 vb = *(const uint4*)(Bt + (size_t)(colBase + r) * 512 + k0 + c * 8);
            *(uint4*)(sB + r * TC_LDA + c * 16) = vb;
        }
        __syncthreads();

#pragma unroll
        for (int ks = 0; ks < 2; ks++) {
            uint32_t afr[4][4];
#pragma unroll
            for (int mt = 0; mt < 4; mt++) {
                uint32_t addr = aAddrBase + (uint32_t)mt * 16 * TC_LDA + ks * 32;
                asm volatile("ldmatrix.sync.aligned.m8n8.x4.shared.b16 {%0,%1,%2,%3}, [%4];"
                             : "=r"(afr[mt][0]), "=r"(afr[mt][1]),
                               "=r"(afr[mt][2]), "=r"(afr[mt][3]) : "r"(addr));
            }
            uint32_t bfr[4][2];
#pragma unroll
            for (int nt = 0; nt < 4; nt++) {
                uint32_t addr = bAddrBase + (uint32_t)nt * 8 * TC_LDA + ks * 32;
                asm volatile("ldmatrix.sync.aligned.m8n8.x2.shared.b16 {%0,%1}, [%2];"
                             : "=r"(bfr[nt][0]), "=r"(bfr[nt][1]) : "r"(addr));
            }
#pragma unroll
            for (int mt = 0; mt < 4; mt++)
#pragma unroll
                for (int nt = 0; nt < 4; nt++)
                    mma16816(acc[mt][nt], afr[mt], bfr[nt], acc[mt][nt]);
        }
        __syncthreads();
    }

#pragma unroll
    for (int mt = 0; mt < 4; mt++) {
#pragma unroll
        for (int nt = 0; nt < 4; nt++) {
            int row0 = rowBase + warp_m * 64 + mt * 16 + (lane >> 2);
            int col  = colBase + warp_n * 32 + nt * 8 + (lane & 3) * 2;
            *(float2*)(C + (size_t)row0 * ldc + col) =
                make_float2(acc[mt][nt][0], acc[mt][nt][1]);
            *(float2*)(C + (size_t)(row0 + 8) * ldc + col) =
                make_float2(acc[mt][nt][2], acc[mt][nt][3]);
        }
    }
}

// ---------------- weight transpose + bf16 convert ---------------------------
__global__ void wconv_kernel(const float* __restrict__ W,
                             __nv_bfloat16* __restrict__ Wt, int N)
{
    __shared__ float tile[32][33];
    int k0 = blockIdx.y * 32, n0 = blockIdx.x * 32;
    int tx = threadIdx.x & 31, ty = threadIdx.x >> 5;
#pragma unroll
    for (int i = 0; i < 32; i += 8)
        tile[ty + i][tx] = W[(size_t)(k0 + ty + i) * N + n0 + tx];
    __syncthreads();
#pragma unroll
    for (int i = 0; i < 32; i += 8)
        Wt[(size_t)(n0 + ty + i) * 512 + k0 + tx] = __float2bfloat16(tile[tx][ty + i]);
}

// ---------------- post-VQ: gather, quantized_st, vq loss, counts, dw -------
__global__ void postvq_kernel(const float* __restrict__ x,
                              const float* __restrict__ emb,
                              float* __restrict__ out_q)
{
    int row = blockIdx.x;
    int idx = (int)(unsigned)(g_best[row] & 0xFFFFFFFFull);
    const float4* xr = (const float4*)(x   + (size_t)row * DDIM);
    const float4* er = (const float4*)(emb + (size_t)idx * DDIM);
    float4 xv = xr[threadIdx.x];
    float4 ev = er[threadIdx.x];
    float4 q;
    q.x = xv.x + (ev.x - xv.x);
    q.y = xv.y + (ev.y - xv.y);
    q.z = xv.z + (ev.z - xv.z);
    q.w = xv.w + (ev.w - xv.w);
    ((float4*)(out_q + (size_t)row * DDIM))[threadIdx.x] = q;

    float dx = xv.x - ev.x, dy = xv.y - ev.y, dz = xv.z - ev.z, dw2 = xv.w - ev.w;
    float s = dx * dx + dy * dy + dz * dz + dw2 * dw2;

    float* dwp = g_dw + (size_t)idx * DDIM + threadIdx.x * 4;
    atomicAdd(dwp + 0, xv.x);
    atomicAdd(dwp + 1, xv.y);
    atomicAdd(dwp + 2, xv.z);
    atomicAdd(dwp + 3, xv.w);

    s = blockReduceSum(s);
    if (threadIdx.x == 0) {
        g_vqrow[row] = 0.25f * s;
        atomicAdd(&g_counts[idx], 1.0f);
    }
}

// ---------------- EMA count + perplexity ------------------------------------
__global__ void ema_kernel(const float* __restrict__ ema_count,
                           float* __restrict__ out_cnt,
                           float* __restrict__ out_perp)
{
    int m = threadIdx.x;
    float c = g_counts[m];
    float nc0 = 0.999f * ema_count[m] + 0.001f * c;
    float n = blockReduceSum(nc0);
    float newc = (nc0 + 1e-5f) / (n + (float)MCODES * 1e-5f) * n;
    out_cnt[m] = newc;
    g_newc[m] = newc;
    float p = c * (1.0f / (float)NROWS);
    float t = p * logf(p + 1e-10f);
    float s = blockReduceSum(t);
    if (m == 0) out_perp[0] = expf(-s);
}

__global__ void embw_kernel(const float* __restrict__ ema_weight,
                            float* __restrict__ out_emb,
                            float* __restrict__ out_w)
{
    int i = blockIdx.x * 256 + threadIdx.x;
    float w = 0.999f * ema_weight[i] + 0.001f * g_dw[i];
    out_w[i] = w;
    out_emb[i] = w / g_newc[i >> 9];
}

// ---------------- LayerNorm + ReLU -> bf16 ----------------------------------
__global__ void ln_relu_bf16_kernel(const float* __restrict__ X,
                                    const float* __restrict__ g,
                                    const float* __restrict__ b,
                                    __nv_bfloat16* __restrict__ Y)
{
    constexpr int W = 512;
    constexpr int PER = 2;
    int row = blockIdx.x;
    const float* x = X + (size_t)row * W;
    float v[PER];
    float s = 0.f;
#pragma unroll
    for (int i = 0; i < PER; i++) { v[i] = x[threadIdx.x + i * 256]; s += v[i]; }
    float mean = blockReduceSum(s) * (1.0f / W);
    float s2 = 0.f;
#pragma unroll
    for (int i = 0; i < PER; i++) { float d = v[i] - mean; s2 += d * d; }
    float var = blockReduceSum(s2) * (1.0f / W);
    float rstd = rsqrtf(var + 1e-5f);
#pragma unroll
    for (int i = 0; i < PER; i++) {
        int c = threadIdx.x + i * 256;
        float o = (v[i] - mean) * rstd * g[c] + b[c];
        Y[(size_t)row * W + c] = __float2bfloat16(fmaxf(o, 0.f));
    }
}

// ---------------- dtype detection -------------------------------------------
__global__ void detect_mask_kernel(const unsigned* __restrict__ m) {
    __shared__ int bad, gt1;
    if (threadIdx.x == 0) { bad = 0; gt1 = 0; }
    __syncthreads();
    for (int i = threadIdx.x; i < 8192; i += blockDim.x) {
        unsigned v = m[i];
        if (v > 1u) {
            atomicOr(&gt1, 1);
            if (v != 0x3F800000u) atomicOr(&bad, 1);
        }
    }
    __syncthreads();
    if (threadIdx.x == 0) g_mask_mode = (gt1 == 0) ? 0 : (bad ? 2 : 1);
}

__global__ void detect_lab_kernel(const unsigned* __restrict__ lab) {
    __shared__ int any_nz;
    if (threadIdx.x == 0) any_nz = 0;
    __syncthreads();
    for (int i = threadIdx.x; i < NROWS / 2; i += blockDim.x) {
        if (lab[2 * i + 1] != 0u) atomicOr(&any_nz, 1);
    }
    __syncthreads();
    if (threadIdx.x == 0) g_lab_mode = any_nz ? 0 : 1;
}

// ---------------- cross-entropy + final loss --------------------------------
__global__ void ce_kernel(const void* __restrict__ labels,
                          const void* __restrict__ mask,
                          float* __restrict__ out_loss)
{
    int row = blockIdx.x;
    const float* lg = g_logits + (size_t)row * MCODES;
    float v[4];
#pragma unroll
    for (int i = 0; i < 4; i++) v[i] = lg[threadIdx.x + i * 256];
    float mx = fmaxf(fmaxf(v[0], v[1]), fmaxf(v[2], v[3]));
    mx = blockReduceMax(mx);
    float s = 0.f;
#pragma unroll
    for (int i = 0; i < 4; i++) s += expf(v[i] - mx);
    s = blockReduceSum(s);
    if (threadIdx.x == 0) {
        float lse = mx + logf(s);
        int lab = g_lab_mode ? (int)((const long long*)labels)[row]
                             : ((const int*)labels)[row];
        int mode = g_mask_mode;
        bool invalid;
        if (mode == 2)      invalid = ((const unsigned char*)mask)[row] != 0;
        else if (mode == 1) invalid = ((const float*)mask)[row] != 0.f;
        else                invalid = ((const int*)mask)[row] != 0;
        float ce = invalid ? 0.f : (lse - lg[lab]);
        out_loss[row] = ce + g_vqrow[row];
    }
}

// ---------------- launch -----------------------------------------------------
extern "C" void kernel_launch(void* const* d_in, const int* in_sizes, int n_in,
                              void* d_out, int out_size)
{
    const float* x         = (const float*)d_in[0];
    const void*  mask      = d_in[1];
    const void*  labels    = d_in[2];
    const float* emb       = (const float*)d_in[3];
    const float* ema_count = (const float*)d_in[4];
    const float* ema_wt    = (const float*)d_in[5];
    const float* ln1g      = (const float*)d_in[6];
    const float* ln1b      = (const float*)d_in[7];
    const float* W1        = (const float*)d_in[8];
    const float* ln2g      = (const float*)d_in[9];
    const float* ln2b      = (const float*)d_in[10];
    const float* W2        = (const float*)d_in[11];

    float* out      = (float*)d_out;
    float* out_q    = out;
    float* out_loss = out + (size_t)NROWS * DDIM;
    float* out_perp = out_loss + NROWS;
    float* out_emb  = out_perp + 1;
    float* out_cnt  = out_emb + (size_t)MCODES * DDIM;
    float* out_w    = out_cnt + MCODES;

    void *pa1, *ph, *pa2, *pxsq, *pesq, *pw1t, *pw2t, *plog, *pxs, *pes;
    cudaGetSymbolAddress(&pa1, g_a1b);
    cudaGetSymbolAddress(&ph, g_h);
    cudaGetSymbolAddress(&pa2, g_a2b);
    cudaGetSymbolAddress(&pxsq, g_xsq);
    cudaGetSymbolAddress(&pesq, g_esq);
    cudaGetSymbolAddress(&pw1t, g_w1t);
    cudaGetSymbolAddress(&pw2t, g_w2t);
    cudaGetSymbolAddress(&plog, g_logits);
    cudaGetSymbolAddress(&pxs, g_xs);
    cudaGetSymbolAddress(&pes, g_es);

    // --- VQ path: bit-exact bucket argmin on tensor cores ---
    init_kernel<<<2048, 256>>>();
    seqsq_kernel<<<MCODES, 128>>>(emb, (float*)pesq);
    seqsq_kernel<<<NROWS, 128>>>(x, (float*)pxsq);
    split3_kernel<<<NROWS * 2, 256>>>(x, (__nv_bfloat16*)pxs, NROWS);
    split3_kernel<<<MCODES * 2, 256>>>(emb, (__nv_bfloat16*)pes, MCODES);
    argmin_tc_kernel<<<dim3(8, 256), 256>>>((const __nv_bfloat16*)pxs,
                                            (const __nv_bfloat16*)pes);
    postvq_kernel<<<NROWS, 128>>>(x, emb, out_q);
    ema_kernel<<<1, 1024>>>(ema_count, out_cnt, out_perp);
    embw_kernel<<<2048, 256>>>(ema_wt, out_emb, out_w);

    // --- decoder path: bf16 tensor-core GEMMs (mma.sync) ---
    wconv_kernel<<<dim3(HDIM / 32, DDIM / 32), 256>>>(W1, (__nv_bfloat16*)pw1t, HDIM);
    wconv_kernel<<<dim3(MCODES / 32, HDIM / 32), 256>>>(W2, (__nv_bfloat16*)pw2t, MCODES);
    ln_relu_bf16_kernel<<<NROWS, 256>>>(x, ln1g, ln1b, (__nv_bfloat16*)pa1);
    tcgemm_kernel<<<dim3(HDIM / 128, 256), 256>>>((const __nv_bfloat16*)pa1,
                                                  (const __nv_bfloat16*)pw1t,
                                                  (float*)ph, HDIM);
    ln_relu_bf16_kernel<<<NROWS, 256>>>((const float*)ph, ln2g, ln2b, (__nv_bfloat16*)pa2);
    tcgemm_kernel<<<dim3(MCODES / 128, 256), 256>>>((const __nv_bfloat16*)pa2,
                                                    (const __nv_bfloat16*)pw2t,
                                                    (float*)plog, MCODES);

    // --- loss ---
    detect_mask_kernel<<<1, 256>>>((const unsigned*)mask);
    detect_lab_kernel<<<1, 256>>>((const unsigned*)labels);
    ce_kernel<<<NROWS, 256>>>(labels, mask, out_loss);
}

// round 8
// speedup vs baseline: 2.7101x; 1.5545x over previous
#include <cuda_runtime.h>
#include <cuda_bf16.h>
#include <cuda_fp16.h>
#include <cstdint>

#define NROWS 32768   // B*T
#define DDIM  512
#define HDIM  512
#define MCODES 1024

// ---------------- scratch (static device allocations; no cudaMalloc) -------
__device__ unsigned long long g_best[NROWS];
__device__ float g_counts[MCODES];
__device__ float g_dw[MCODES * DDIM];
__device__ float g_esq[MCODES];
__device__ float g_xsq[NROWS];
__device__ float g_vqrow[NROWS];
__device__ float g_newc[MCODES];
__device__ int   g_mask_mode;
__device__ int   g_lab_mode;     // 0 = int32, 1 = int64
__device__ __align__(16) __half g_xs[(size_t)NROWS * 1024];    // 16*x 2-way fp16 split
__device__ __align__(16) __half g_es[(size_t)MCODES * 1024];   // 4096*e 2-way fp16 split
__device__ __align__(16) __nv_bfloat16 g_a1b[(size_t)NROWS * DDIM];
__device__ __align__(16) __nv_bfloat16 g_a2b[(size_t)NROWS * HDIM];
__device__ __align__(16) __nv_bfloat16 g_w1t[(size_t)HDIM * DDIM];     // [N=512, K=512]
__device__ __align__(16) __nv_bfloat16 g_w2t[(size_t)MCODES * HDIM];   // [N=1024, K=512]
__device__ float g_h[(size_t)NROWS * HDIM];
__device__ float g_logits[(size_t)NROWS * MCODES];

// ---------------- reduction helpers ----------------------------------------
__device__ __forceinline__ float warpReduceSum(float v) {
#pragma unroll
    for (int o = 16; o > 0; o >>= 1) v += __shfl_down_sync(0xffffffffu, v, o);
    return v;
}
__device__ __forceinline__ float warpReduceMax(float v) {
#pragma unroll
    for (int o = 16; o > 0; o >>= 1) v = fmaxf(v, __shfl_down_sync(0xffffffffu, v, o));
    return v;
}
__device__ __forceinline__ float blockReduceSum(float v) {
    __shared__ float s[32];
    __syncthreads();
    v = warpReduceSum(v);
    int lane = threadIdx.x & 31, w = threadIdx.x >> 5;
    if (lane == 0) s[w] = v;
    __syncthreads();
    int nw = blockDim.x >> 5;
    float r = (threadIdx.x < nw) ? s[threadIdx.x] : 0.f;
    if (w == 0) { r = warpReduceSum(r); if (lane == 0) s[0] = r; }
    __syncthreads();
    return s[0];
}
__device__ __forceinline__ float blockReduceMax(float v) {
    __shared__ float s[32];
    __syncthreads();
    v = warpReduceMax(v);
    int lane = threadIdx.x & 31, w = threadIdx.x >> 5;
    if (lane == 0) s[w] = v;
    __syncthreads();
    int nw = blockDim.x >> 5;
    float r = (threadIdx.x < nw) ? s[threadIdx.x] : __int_as_float(0xff800000);
    if (w == 0) { r = warpReduceMax(r); if (lane == 0) s[0] = r; }
    __syncthreads();
    return s[0];
}
__device__ __forceinline__ unsigned fkey(float f) {
    unsigned u = __float_as_uint(f);
    return (u & 0x80000000u) ? ~u : (u | 0x80000000u);
}
__device__ __forceinline__ uint32_t smem_addr_u32(const void* p) {
    return (uint32_t)__cvta_generic_to_shared(p);
}

// ---------------- init ------------------------------------------------------
__global__ void init_kernel() {
    int i = blockIdx.x * blockDim.x + threadIdx.x;   // grid covers 524288
    if (i < NROWS)  g_best[i]   = ~0ull;
    if (i < MCODES) g_counts[i] = 0.f;
    g_dw[i] = 0.f;
}

// Strict sequential fp32 sum of squares per row (reference rounding order).
__global__ void seqsq_kernel(const float* __restrict__ X, float* __restrict__ out) {
    __shared__ float row[DDIM];
    const float4* src = (const float4*)(X + (size_t)blockIdx.x * DDIM);
    ((float4*)row)[threadIdx.x] = src[threadIdx.x];
    __syncthreads();
    if (threadIdx.x == 0) {
        float s = 0.f;
#pragma unroll 8
        for (int i = 0; i < DDIM; i++)
            s = __fadd_rn(s, __fmul_rn(row[i], row[i]));
        out[blockIdx.x] = s;
    }
}

// 2-way fp16 split of scale*v: v_s = h0 + h1 (+ ~2^-22 residual)
__global__ void split2_kernel(const float* __restrict__ V,
                              __half* __restrict__ S, float scale)
{
    int i = blockIdx.x * 256 + threadIdx.x;          // over nrows*512
    int row = i >> 9, col = i & 511;
    float v = V[i] * scale;
    __half h0 = __float2half_rn(v);
    float r1 = v - __half2float(h0);
    __half h1 = __float2half_rn(r1);
    size_t base = (size_t)row * 1024 + col;
    S[base]       = h0;
    S[base + 512] = h1;
}

// ---------------- mma / cp.async helpers ------------------------------------
template<bool USE_HALF>
__device__ __forceinline__ void mma16816t(float* d, const uint32_t* a,
                                          const uint32_t* b) {
    if (USE_HALF)
        asm volatile(
            "mma.sync.aligned.m16n8k16.row.col.f32.f16.f16.f32 "
            "{%0,%1,%2,%3}, {%4,%5,%6,%7}, {%8,%9}, {%0,%1,%2,%3};"
            : "+f"(d[0]), "+f"(d[1]), "+f"(d[2]), "+f"(d[3])
            : "r"(a[0]), "r"(a[1]), "r"(a[2]), "r"(a[3]), "r"(b[0]), "r"(b[1]));
    else
        asm volatile(
            "mma.sync.aligned.m16n8k16.row.col.f32.bf16.bf16.f32 "
            "{%0,%1,%2,%3}, {%4,%5,%6,%7}, {%8,%9}, {%0,%1,%2,%3};"
            : "+f"(d[0]), "+f"(d[1]), "+f"(d[2]), "+f"(d[3])
            : "r"(a[0]), "r"(a[1]), "r"(a[2]), "r"(a[3]), "r"(b[0]), "r"(b[1]));
}

__device__ __forceinline__ void cpasync16(uint32_t dst, const void* src) {
    asm volatile("cp.async.cg.shared.global [%0], [%1], 16;"
                 :: "r"(dst), "l"(src) : "memory");
}

// swizzled smem offset for 16B chunk (row r, chunk c of 4): 64B logical rows,
// 128B macro-rows, XOR swizzle -> 8-row ldmatrix groups are conflict-free.
__device__ __forceinline__ uint32_t swoff(int r, int c) {
    return ((uint32_t)(r >> 1) << 7) |
           ((uint32_t)((((r & 1) << 2) | c) ^ ((r >> 1) & 7)) << 4);
}

template<int NSEG>
__device__ __forceinline__ void tcg_load(
    const uint16_t* A, int ldA, const uint16_t* B, int ldB,
    int rowBase, int colBase, uint32_t sbase, int st, int it, int tid)
{
    int seg = it >> 4, kk = (it & 15) * 32;
    int sa = 0, sb = 0;
    if (NSEG == 3) { sa = (seg == 2) ? 512 : 0; sb = (seg == 1) ? 512 : 0; }
    uint32_t base = sbase + st * 24576;
#pragma unroll
    for (int j = 0; j < 4; j++) {          // A: 256 rows x 4 chunks
        int ch = tid + j * 256, r = ch >> 2, c = ch & 3;
        cpasync16(base + swoff(r, c),
                  A + (size_t)(rowBase + r) * ldA + sa + kk + c * 8);
    }
#pragma unroll
    for (int j = 0; j < 2; j++) {          // B: 128 rows x 4 chunks
        int ch = tid + j * 256, r = ch >> 2, c = ch & 3;
        cpasync16(base + 16384 + swoff(r, c),
                  B + (size_t)(colBase + r) * ldB + sb + kk + c * 8);
    }
    asm volatile("cp.async.commit_group;" ::: "memory");
}

// ---------------- 256x128 double-buffered tensor-core GEMM ------------------
// C[M,N] = A[M,K] @ B[N,K]^T over NSEG K-segments of 512.
// ARGMIN: fused bucket-rounded argmin epilogue (acc scaled by 2^16).
template<int NSEG, bool ARGMIN, bool USE_HALF>
__global__ void __launch_bounds__(256) tcg256_kernel(
    const uint16_t* __restrict__ A, int ldA,
    const uint16_t* __restrict__ B, int ldB,
    float* __restrict__ C, int ldc)
{
    __shared__ __align__(16) unsigned char smem_s[49152];   // 2 stages x 24KB
    const int tid = threadIdx.x, lane = tid & 31, wid = tid >> 5;
    const int warp_m = wid & 3, warp_n = wid >> 2;   // 4m x 2n warps
    const int rowBase = blockIdx.y * 256;
    const int colBase = blockIdx.x * 128;
    const uint32_t sbase = smem_addr_u32(smem_s);

    float acc[4][8][4];
#pragma unroll
    for (int i = 0; i < 4; i++)
#pragma unroll
        for (int j = 0; j < 8; j++)
#pragma unroll
            for (int q = 0; q < 4; q++) acc[i][j][q] = 0.f;

    // precompute ldmatrix offsets (stage-relative)
    uint32_t offA[4][2], offB[4][2];
#pragma unroll
    for (int mt = 0; mt < 4; mt++) {
        int r = warp_m * 64 + mt * 16 + (lane & 15);
#pragma unroll
        for (int ks = 0; ks < 2; ks++)
            offA[mt][ks] = swoff(r, ks * 2 + (lane >> 4));
    }
#pragma unroll
    for (int p = 0; p < 4; p++) {
        int r = warp_n * 64 + p * 16 + (lane & 15);
#pragma unroll
        for (int ks = 0; ks < 2; ks++)
            offB[p][ks] = 16384u + swoff(r, ks * 2 + (lane >> 4));
    }

    const int nch = NSEG * 16;
    tcg_load<NSEG>(A, ldA, B, ldB, rowBase, colBase, sbase, 0, 0, tid);

#pragma unroll 1
    for (int i = 0; i < nch; i++) {
        if (i + 1 < nch) {
            tcg_load<NSEG>(A, ldA, B, ldB, rowBase, colBase, sbase,
                           (i + 1) & 1, i + 1, tid);
            asm volatile("cp.async.wait_group 1;" ::: "memory");
        } else {
            asm volatile("cp.async.wait_group 0;" ::: "memory");
        }
        __syncthreads();

        uint32_t stB = sbase + (uint32_t)(i & 1) * 24576u;
#pragma unroll
        for (int ks = 0; ks < 2; ks++) {
            uint32_t af[4][4];
#pragma unroll
            for (int mt = 0; mt < 4; mt++) {
                uint32_t ad = stB + offA[mt][ks];
                asm volatile("ldmatrix.sync.aligned.m8n8.x4.shared.b16 {%0,%1,%2,%3}, [%4];"
                             : "=r"(af[mt][0]), "=r"(af[mt][1]),
                               "=r"(af[mt][2]), "=r"(af[mt][3]) : "r"(ad));
            }
            uint32_t bf[8][2];
#pragma unroll
            for (int p = 0; p < 4; p++) {
                uint32_t bd = stB + offB[p][ks];
                uint32_t q0, q1, q2, q3;
                asm volatile("ldmatrix.sync.aligned.m8n8.x4.shared.b16 {%0,%1,%2,%3}, [%4];"
                             : "=r"(q0), "=r"(q1), "=r"(q2), "=r"(q3) : "r"(bd));
                bf[2 * p][0] = q0; bf[2 * p][1] = q2;
                bf[2 * p + 1][0] = q1; bf[2 * p + 1][1] = q3;
            }
#pragma unroll
            for (int mt = 0; mt < 4; mt++)
#pragma unroll
                for (int nt = 0; nt < 8; nt++)
                    mma16816t<USE_HALF>(acc[mt][nt], af[mt], bf[nt]);
        }
        __syncthreads();
    }

    if (ARGMIN) {
        // acc holds 65536 * (x . e); d = fl(fl(esq+xsq) - 2*(acc/65536))
        const float INV = 1.0f / 65536.0f;
        const int rq = lane >> 2;
#pragma unroll
        for (int mt = 0; mt < 4; mt++) {
#pragma unroll
            for (int half = 0; half < 2; half++) {
                int row = rowBase + warp_m * 64 + mt * 16 + rq + half * 8;
                float xs = g_xsq[row];
                float bd = __int_as_float(0x7f800000);
                int bc = 0;
#pragma unroll
                for (int nt = 0; nt < 8; nt++) {
#pragma unroll
                    for (int q = 0; q < 2; q++) {
                        int col = colBase + warp_n * 64 + nt * 8 + (lane & 3) * 2 + q;
                        float a = acc[mt][nt][half * 2 + q] * INV;
                        float t1 = __fadd_rn(g_esq[col], xs);
                        float d  = __fadd_rn(t1, -2.0f * a);
                        if (d < bd) { bd = d; bc = col; }
                    }
                }
                unsigned long long key =
                    ((unsigned long long)fkey(bd) << 32) | (unsigned)bc;
                unsigned long long o1 = __shfl_xor_sync(0xffffffffu, key, 1);
                if (o1 < key) key = o1;
                unsigned long long o2 = __shfl_xor_sync(0xffffffffu, key, 2);
                if (o2 < key) key = o2;
                if ((lane & 3) == 0) atomicMin(&g_best[row], key);
            }
        }
    } else {
#pragma unroll
        for (int mt = 0; mt < 4; mt++) {
#pragma unroll
            for (int nt = 0; nt < 8; nt++) {
                int row0 = rowBase + warp_m * 64 + mt * 16 + (lane >> 2);
                int col  = colBase + warp_n * 64 + nt * 8 + (lane & 3) * 2;
                *(float2*)(C + (size_t)row0 * ldc + col) =
                    make_float2(acc[mt][nt][0], acc[mt][nt][1]);
                *(float2*)(C + (size_t)(row0 + 8) * ldc + col) =
                    make_float2(acc[mt][nt][2], acc[mt][nt][3]);
            }
        }
    }
}

// ---------------- weight transpose + bf16 convert ---------------------------
__global__ void wconv_kernel(const float* __restrict__ W,
                             __nv_bfloat16* __restrict__ Wt, int N)
{
    __shared__ float tile[32][33];
    int k0 = blockIdx.y * 32, n0 = blockIdx.x * 32;
    int tx = threadIdx.x & 31, ty = threadIdx.x >> 5;
#pragma unroll
    for (int i = 0; i < 32; i += 8)
        tile[ty + i][tx] = W[(size_t)(k0 + ty + i) * N + n0 + tx];
    __syncthreads();
#pragma unroll
    for (int i = 0; i < 32; i += 8)
        Wt[(size_t)(n0 + ty + i) * 512 + k0 + tx] = __float2bfloat16(tile[tx][ty + i]);
}

// ---------------- post-VQ: gather, quantized_st, vq loss, counts, dw -------
__global__ void postvq_kernel(const float* __restrict__ x,
                              const float* __restrict__ emb,
                              float* __restrict__ out_q)
{
    int row = blockIdx.x;
    int idx = (int)(unsigned)(g_best[row] & 0xFFFFFFFFull);
    const float4* xr = (const float4*)(x   + (size_t)row * DDIM);
    const float4* er = (const float4*)(emb + (size_t)idx * DDIM);
    float4 xv = xr[threadIdx.x];
    float4 ev = er[threadIdx.x];
    float4 q;
    q.x = xv.x + (ev.x - xv.x);
    q.y = xv.y + (ev.y - xv.y);
    q.z = xv.z + (ev.z - xv.z);
    q.w = xv.w + (ev.w - xv.w);
    ((float4*)(out_q + (size_t)row * DDIM))[threadIdx.x] = q;

    float dx = xv.x - ev.x, dy = xv.y - ev.y, dz = xv.z - ev.z, dw2 = xv.w - ev.w;
    float s = dx * dx + dy * dy + dz * dz + dw2 * dw2;

    float* dwp = g_dw + (size_t)idx * DDIM + threadIdx.x * 4;
    atomicAdd(dwp + 0, xv.x);
    atomicAdd(dwp + 1, xv.y);
    atomicAdd(dwp + 2, xv.z);
    atomicAdd(dwp + 3, xv.w);

    s = blockReduceSum(s);
    if (threadIdx.x == 0) {
        g_vqrow[row] = 0.25f * s;
        atomicAdd(&g_counts[idx], 1.0f);
    }
}

// ---------------- EMA count + perplexity ------------------------------------
__global__ void ema_kernel(const float* __restrict__ ema_count,
                           float* __restrict__ out_cnt,
                           float* __restrict__ out_perp)
{
    int m = threadIdx.x;
    float c = g_counts[m];
    float nc0 = 0.999f * ema_count[m] + 0.001f * c;
    float n = blockReduceSum(nc0);
    float newc = (nc0 + 1e-5f) / (n + (float)MCODES * 1e-5f) * n;
    out_cnt[m] = newc;
    g_newc[m] = newc;
    float p = c * (1.0f / (float)NROWS);
    float t = p * logf(p + 1e-10f);
    float s = blockReduceSum(t);
    if (m == 0) out_perp[0] = expf(-s);
}

__global__ void embw_kernel(const float* __restrict__ ema_weight,
                            float* __restrict__ out_emb,
                            float* __restrict__ out_w)
{
    int i = blockIdx.x * 256 + threadIdx.x;
    float w = 0.999f * ema_weight[i] + 0.001f * g_dw[i];
    out_w[i] = w;
    out_emb[i] = w / g_newc[i >> 9];
}

// ---------------- LayerNorm + ReLU -> bf16 ----------------------------------
__global__ void ln_relu_bf16_kernel(const float* __restrict__ X,
                                    const float* __restrict__ g,
                                    const float* __restrict__ b,
                                    __nv_bfloat16* __restrict__ Y)
{
    constexpr int W = 512;
    constexpr int PER = 2;
    int row = blockIdx.x;
    const float* x = X + (size_t)row * W;
    float v[PER];
    float s = 0.f;
#pragma unroll
    for (int i = 0; i < PER; i++) { v[i] = x[threadIdx.x + i * 256]; s += v[i]; }
    float mean = blockReduceSum(s) * (1.0f / W);
    float s2 = 0.f;
#pragma unroll
    for (int i = 0; i < PER; i++) { float d = v[i] - mean; s2 += d * d; }
    float var = blockReduceSum(s2) * (1.0f / W);
    float rstd = rsqrtf(var + 1e-5f);
#pragma unroll
    for (int i = 0; i < PER; i++) {
        int c = threadIdx.x + i * 256;
        float o = (v[i] - mean) * rstd * g[c] + b[c];
        Y[(size_t)row * W + c] = __float2bfloat16(fmaxf(o, 0.f));
    }
}

// ---------------- dtype detection -------------------------------------------
__global__ void detect_mask_kernel(const unsigned* __restrict__ m) {
    __shared__ int bad, gt1;
    if (threadIdx.x == 0) { bad = 0; gt1 = 0; }
    __syncthreads();
    for (int i = threadIdx.x; i < 8192; i += blockDim.x) {
        unsigned v = m[i];
        if (v > 1u) {
            atomicOr(&gt1, 1);
            if (v != 0x3F800000u) atomicOr(&bad, 1);
        }
    }
    __syncthreads();
    if (threadIdx.x == 0) g_mask_mode = (gt1 == 0) ? 0 : (bad ? 2 : 1);
}

__global__ void detect_lab_kernel(const unsigned* __restrict__ lab) {
    __shared__ int any_nz;
    if (threadIdx.x == 0) any_nz = 0;
    __syncthreads();
    for (int i = threadIdx.x; i < NROWS / 2; i += blockDim.x) {
        if (lab[2 * i + 1] != 0u) atomicOr(&any_nz, 1);
    }
    __syncthreads();
    if (threadIdx.x == 0) g_lab_mode = any_nz ? 0 : 1;
}

// ---------------- cross-entropy + final loss --------------------------------
__global__ void ce_kernel(const void* __restrict__ labels,
                          const void* __restrict__ mask,
                          float* __restrict__ out_loss)
{
    int row = blockIdx.x;
    const float* lg = g_logits + (size_t)row * MCODES;
    float v[4];
#pragma unroll
    for (int i = 0; i < 4; i++) v[i] = lg[threadIdx.x + i * 256];
    float mx = fmaxf(fmaxf(v[0], v[1]), fmaxf(v[2], v[3]));
    mx = blockReduceMax(mx);
    float s = 0.f;
#pragma unroll
    for (int i = 0; i < 4; i++) s += expf(v[i] - mx);
    s = blockReduceSum(s);
    if (threadIdx.x == 0) {
        float lse = mx + logf(s);
        int lab = g_lab_mode ? (int)((const long long*)labels)[row]
                             : ((const int*)labels)[row];
        int mode = g_mask_mode;
        bool invalid;
        if (mode == 2)      invalid = ((const unsigned char*)mask)[row] != 0;
        else if (mode == 1) invalid = ((const float*)mask)[row] != 0.f;
        else                invalid = ((const int*)mask)[row] != 0;
        float ce = invalid ? 0.f : (lse - lg[lab]);
        out_loss[row] = ce + g_vqrow[row];
    }
}

// ---------------- launch -----------------------------------------------------
extern "C" void kernel_launch(void* const* d_in, const int* in_sizes, int n_in,
                              void* d_out, int out_size)
{
    const float* x         = (const float*)d_in[0];
    const void*  mask      = d_in[1];
    const void*  labels    = d_in[2];
    const float* emb       = (const float*)d_in[3];
    const float* ema_count = (const float*)d_in[4];
    const float* ema_wt    = (const float*)d_in[5];
    const float* ln1g      = (const float*)d_in[6];
    const float* ln1b      = (const float*)d_in[7];
    const float* W1        = (const float*)d_in[8];
    const float* ln2g      = (const float*)d_in[9];
    const float* ln2b      = (const float*)d_in[10];
    const float* W2        = (const float*)d_in[11];

    float* out      = (float*)d_out;
    float* out_q    = out;
    float* out_loss = out + (size_t)NROWS * DDIM;
    float* out_perp = out_loss + NROWS;
    float* out_emb  = out_perp + 1;
    float* out_cnt  = out_emb + (size_t)MCODES * DDIM;
    float* out_w    = out_cnt + MCODES;

    void *pa1, *ph, *pa2, *pxsq, *pesq, *pw1t, *pw2t, *plog, *pxs, *pes;
    cudaGetSymbolAddress(&pa1, g_a1b);
    cudaGetSymbolAddress(&ph, g_h);
    cudaGetSymbolAddress(&pa2, g_a2b);
    cudaGetSymbolAddress(&pxsq, g_xsq);
    cudaGetSymbolAddress(&pesq, g_esq);
    cudaGetSymbolAddress(&pw1t, g_w1t);
    cudaGetSymbolAddress(&pw2t, g_w2t);
    cudaGetSymbolAddress(&plog, g_logits);
    cudaGetSymbolAddress(&pxs, g_xs);
    cudaGetSymbolAddress(&pes, g_es);

    // --- VQ path: bucket-exact argmin on tensor cores (fp16 3-term split) ---
    init_kernel<<<2048, 256>>>();
    seqsq_kernel<<<MCODES, 128>>>(emb, (float*)pesq);
    seqsq_kernel<<<NROWS, 128>>>(x, (float*)pxsq);
    split2_kernel<<<NROWS * 2, 256>>>(x, (__half*)pxs, 16.0f);
    split2_kernel<<<MCODES * 2, 256>>>(emb, (__half*)pes, 4096.0f);
    tcg256_kernel<3, true, true><<<dim3(MCODES / 128, NROWS / 256), 256>>>(
        (const uint16_t*)pxs, 1024, (const uint16_t*)pes, 1024, nullptr, 0);
    postvq_kernel<<<NROWS, 128>>>(x, emb, out_q);
    ema_kernel<<<1, 1024>>>(ema_count, out_cnt, out_perp);
    embw_kernel<<<2048, 256>>>(ema_wt, out_emb, out_w);

    // --- decoder path: bf16 tensor-core GEMMs (double-buffered) ---
    wconv_kernel<<<dim3(HDIM / 32, DDIM / 32), 256>>>(W1, (__nv_bfloat16*)pw1t, HDIM);
    wconv_kernel<<<dim3(MCODES / 32, HDIM / 32), 256>>>(W2, (__nv_bfloat16*)pw2t, MCODES);
    ln_relu_bf16_kernel<<<NROWS, 256>>>(x, ln1g, ln1b, (__nv_bfloat16*)pa1);
    tcg256_kernel<1, false, false><<<dim3(HDIM / 128, NROWS / 256), 256>>>(
        (const uint16_t*)pa1, 512, (const uint16_t*)pw1t, 512, (float*)ph, HDIM);
    ln_relu_bf16_kernel<<<NROWS, 256>>>((const float*)ph, ln2g, ln2b, (__nv_bfloat16*)pa2);
    tcg256_kernel<1, false, false><<<dim3(MCODES / 128, NROWS / 256), 256>>>(
        (const uint16_t*)pa2, 512, (const uint16_t*)pw2t, 512, (float*)plog, MCODES);

    // --- loss ---
    detect_mask_kernel<<<1, 256>>>((const unsigned*)mask);
    detect_lab_kernel<<<1, 256>>>((const unsigned*)labels);
    ce_kernel<<<NROWS, 256>>>(labels, mask, out_loss);
}

// round 10
// speedup vs baseline: 2.9466x; 1.0873x over previous
#include <cuda_runtime.h>
#include <cuda_bf16.h>
#include <cuda_fp16.h>
#include <cstdint>

#define NROWS 32768   // B*T
#define DDIM  512
#define HDIM  512
#define MCODES 1024

// ---------------- scratch (static device allocations; no cudaMalloc) -------
__device__ unsigned long long g_best[NROWS];
__device__ float g_counts[MCODES];
__device__ float g_esq[MCODES];
__device__ float g_xsq[NROWS];
__device__ float g_vqrow[NROWS];
__device__ float g_newc[MCODES];
__device__ int   g_mask_mode;
__device__ int   g_lab_mode;     // 0 = int32, 1 = int64
__device__ int   g_labi[NROWS];
__device__ int   g_cnti[MCODES];
__device__ int   g_off[MCODES];
__device__ int   g_fill[MCODES];
__device__ int   g_rows[NROWS];
__device__ float g_pmax[(size_t)NROWS * 16];
__device__ float g_psum[(size_t)NROWS * 16];
__device__ float g_labv[NROWS];
__device__ __align__(16) __half g_xs[(size_t)NROWS * 1024];    // 16*x 2-way fp16 split
__device__ __align__(16) __half g_es[(size_t)MCODES * 1024];   // 4096*e 2-way fp16 split
__device__ __align__(16) __nv_bfloat16 g_a1b[(size_t)NROWS * DDIM];
__device__ __align__(16) __nv_bfloat16 g_a2b[(size_t)NROWS * HDIM];
__device__ __align__(16) __nv_bfloat16 g_w1t[(size_t)HDIM * DDIM];     // [N=512, K=512]
__device__ __align__(16) __nv_bfloat16 g_w2t[(size_t)MCODES * HDIM];   // [N=1024, K=512]
__device__ float g_h[(size_t)NROWS * HDIM];

// ---------------- reduction helpers ----------------------------------------
__device__ __forceinline__ float warpReduceSum(float v) {
#pragma unroll
    for (int o = 16; o > 0; o >>= 1) v += __shfl_down_sync(0xffffffffu, v, o);
    return v;
}
__device__ __forceinline__ float blockReduceSum(float v) {
    __shared__ float s[32];
    __syncthreads();
    v = warpReduceSum(v);
    int lane = threadIdx.x & 31, w = threadIdx.x >> 5;
    if (lane == 0) s[w] = v;
    __syncthreads();
    int nw = blockDim.x >> 5;
    float r = (threadIdx.x < nw) ? s[threadIdx.x] : 0.f;
    if (w == 0) { r = warpReduceSum(r); if (lane == 0) s[0] = r; }
    __syncthreads();
    return s[0];
}
__device__ __forceinline__ unsigned fkey(float f) {
    unsigned u = __float_as_uint(f);
    return (u & 0x80000000u) ? ~u : (u | 0x80000000u);
}
__device__ __forceinline__ uint32_t smem_addr_u32(const void* p) {
    return (uint32_t)__cvta_generic_to_shared(p);
}

// ---------------- init ------------------------------------------------------
__global__ void init_kernel() {
    int i = blockIdx.x * blockDim.x + threadIdx.x;   // grid covers 32768
    g_best[i] = ~0ull;
    if (i < MCODES) { g_cnti[i] = 0; g_fill[i] = 0; }
}

// Strict sequential fp32 sum of squares per row (reference rounding order).
__global__ void seqsq_kernel(const float* __restrict__ X, float* __restrict__ out) {
    __shared__ float row[DDIM];
    const float4* src = (const float4*)(X + (size_t)blockIdx.x * DDIM);
    ((float4*)row)[threadIdx.x] = src[threadIdx.x];
    __syncthreads();
    if (threadIdx.x == 0) {
        float s = 0.f;
#pragma unroll 8
        for (int i = 0; i < DDIM; i++)
            s = __fadd_rn(s, __fmul_rn(row[i], row[i]));
        out[blockIdx.x] = s;
    }
}

// 2-way fp16 split of scale*v, vectorized: 4 elems per thread
__global__ void split2_kernel(const float4* __restrict__ V,
                              __half* __restrict__ S, float scale)
{
    int i = blockIdx.x * 256 + threadIdx.x;          // over nrows*128
    int row = i >> 7, c4 = i & 127;
    float4 v = V[i];
    struct __align__(8) H4 { __half h[4]; } h0, h1;
    float vv[4] = {v.x * scale, v.y * scale, v.z * scale, v.w * scale};
#pragma unroll
    for (int k = 0; k < 4; k++) {
        __half a = __float2half_rn(vv[k]);
        h0.h[k] = a;
        h1.h[k] = __float2half_rn(vv[k] - __half2float(a));
    }
    size_t base = (size_t)row * 1024 + c4 * 4;
    *(uint2*)(S + base)       = *(uint2*)&h0;
    *(uint2*)(S + base + 512) = *(uint2*)&h1;
}

// ---------------- mma / cp.async helpers ------------------------------------
template<bool USE_HALF>
__device__ __forceinline__ void mma16816t(float* d, const uint32_t* a,
                                          const uint32_t* b) {
    if (USE_HALF)
        asm volatile(
            "mma.sync.aligned.m16n8k16.row.col.f32.f16.f16.f32 "
            "{%0,%1,%2,%3}, {%4,%5,%6,%7}, {%8,%9}, {%0,%1,%2,%3};"
            : "+f"(d[0]), "+f"(d[1]), "+f"(d[2]), "+f"(d[3])
            : "r"(a[0]), "r"(a[1]), "r"(a[2]), "r"(a[3]), "r"(b[0]), "r"(b[1]));
    else
        asm volatile(
            "mma.sync.aligned.m16n8k16.row.col.f32.bf16.bf16.f32 "
            "{%0,%1,%2,%3}, {%4,%5,%6,%7}, {%8,%9}, {%0,%1,%2,%3};"
            : "+f"(d[0]), "+f"(d[1]), "+f"(d[2]), "+f"(d[3])
            : "r"(a[0]), "r"(a[1]), "r"(a[2]), "r"(a[3]), "r"(b[0]), "r"(b[1]));
}

__device__ __forceinline__ void cpasync16(uint32_t dst, const void* src) {
    asm volatile("cp.async.cg.shared.global [%0], [%1], 16;"
                 :: "r"(dst), "l"(src) : "memory");
}

__device__ __forceinline__ uint32_t swoff(int r, int c) {
    return ((uint32_t)(r >> 1) << 7) |
           ((uint32_t)((((r & 1) << 2) | c) ^ ((r >> 1) & 7)) << 4);
}

template<int NSEG>
__device__ __forceinline__ void tcg_load(
    const uint16_t* A, int ldA, const uint16_t* B, int ldB,
    int rowBase, int colBase, uint32_t sbase, int st, int it, int tid)
{
    int seg = it >> 4, kk = (it & 15) * 32;
    int sa = 0, sb = 0;
    if (NSEG == 3) { sa = (seg == 2) ? 512 : 0; sb = (seg == 1) ? 512 : 0; }
    uint32_t base = sbase + st * 24576;
#pragma unroll
    for (int j = 0; j < 4; j++) {          // A: 256 rows x 4 chunks
        int ch = tid + j * 256, r = ch >> 2, c = ch & 3;
        cpasync16(base + swoff(r, c),
                  A + (size_t)(rowBase + r) * ldA + sa + kk + c * 8);
    }
#pragma unroll
    for (int j = 0; j < 2; j++) {          // B: 128 rows x 4 chunks
        int ch = tid + j * 256, r = ch >> 2, c = ch & 3;
        cpasync16(base + 16384 + swoff(r, c),
                  B + (size_t)(colBase + r) * ldB + sb + kk + c * 8);
    }
    asm volatile("cp.async.commit_group;" ::: "memory");
}

// ---------------- 256x128 double-buffered tensor-core GEMM ------------------
// EPI: 0 = store C, 1 = fused bucket-argmin (acc scaled 2^16), 2 = fused CE.
template<int NSEG, int EPI, bool USE_HALF>
__global__ void __launch_bounds__(256) tcg256_kernel(
    const uint16_t* __restrict__ A, int ldA,
    const uint16_t* __restrict__ B, int ldB,
    float* __restrict__ C, int ldc)
{
    __shared__ __align__(16) unsigned char smem_s[49152];   // 2 stages x 24KB
    const int tid = threadIdx.x, lane = tid & 31, wid = tid >> 5;
    const int warp_m = wid & 3, warp_n = wid >> 2;   // 4m x 2n warps
    const int rowBase = blockIdx.y * 256;
    const int colBase = blockIdx.x * 128;
    const uint32_t sbase = smem_addr_u32(smem_s);

    float acc[4][8][4];
#pragma unroll
    for (int i = 0; i < 4; i++)
#pragma unroll
        for (int j = 0; j < 8; j++)
#pragma unroll
            for (int q = 0; q < 4; q++) acc[i][j][q] = 0.f;

    uint32_t offA[4][2], offB[4][2];
#pragma unroll
    for (int mt = 0; mt < 4; mt++) {
        int r = warp_m * 64 + mt * 16 + (lane & 15);
#pragma unroll
        for (int ks = 0; ks < 2; ks++)
            offA[mt][ks] = swoff(r, ks * 2 + (lane >> 4));
    }
#pragma unroll
    for (int p = 0; p < 4; p++) {
        int r = warp_n * 64 + p * 16 + (lane & 15);
#pragma unroll
        for (int ks = 0; ks < 2; ks++)
            offB[p][ks] = 16384u + swoff(r, ks * 2 + (lane >> 4));
    }

    const int nch = NSEG * 16;
    tcg_load<NSEG>(A, ldA, B, ldB, rowBase, colBase, sbase, 0, 0, tid);

#pragma unroll 1
    for (int i = 0; i < nch; i++) {
        if (i + 1 < nch) {
            tcg_load<NSEG>(A, ldA, B, ldB, rowBase, colBase, sbase,
                           (i + 1) & 1, i + 1, tid);
            asm volatile("cp.async.wait_group 1;" ::: "memory");
        } else {
            asm volatile("cp.async.wait_group 0;" ::: "memory");
        }
        __syncthreads();

        uint32_t stB = sbase + (uint32_t)(i & 1) * 24576u;
#pragma unroll
        for (int ks = 0; ks < 2; ks++) {
            uint32_t af[4][4];
#pragma unroll
            for (int mt = 0; mt < 4; mt++) {
                uint32_t ad = stB + offA[mt][ks];
                asm volatile("ldmatrix.sync.aligned.m8n8.x4.shared.b16 {%0,%1,%2,%3}, [%4];"
                             : "=r"(af[mt][0]), "=r"(af[mt][1]),
                               "=r"(af[mt][2]), "=r"(af[mt][3]) : "r"(ad));
            }
            uint32_t bf[8][2];
#pragma unroll
            for (int p = 0; p < 4; p++) {
                uint32_t bd = stB + offB[p][ks];
                uint32_t q0, q1, q2, q3;
                asm volatile("ldmatrix.sync.aligned.m8n8.x4.shared.b16 {%0,%1,%2,%3}, [%4];"
                             : "=r"(q0), "=r"(q1), "=r"(q2), "=r"(q3) : "r"(bd));
                bf[2 * p][0] = q0; bf[2 * p][1] = q2;
                bf[2 * p + 1][0] = q1; bf[2 * p + 1][1] = q3;
            }
#pragma unroll
            for (int mt = 0; mt < 4; mt++)
#pragma unroll
                for (int nt = 0; nt < 8; nt++)
                    mma16816t<USE_HALF>(acc[mt][nt], af[mt], bf[nt]);
        }
        __syncthreads();
    }

    if (EPI == 1) {
        // acc holds 65536 * (x . e); d = fl(fl(esq+xsq) - 2*(acc/65536))
        const float INV = 1.0f / 65536.0f;
        const int rq = lane >> 2;
#pragma unroll
        for (int mt = 0; mt < 4; mt++) {
#pragma unroll
            for (int half = 0; half < 2; half++) {
                int row = rowBase + warp_m * 64 + mt * 16 + rq + half * 8;
                float xs = g_xsq[row];
                float bd = __int_as_float(0x7f800000);
                int bc = 0;
#pragma unroll
                for (int nt = 0; nt < 8; nt++) {
#pragma unroll
                    for (int q = 0; q < 2; q++) {
                        int col = colBase + warp_n * 64 + nt * 8 + (lane & 3) * 2 + q;
                        float a = acc[mt][nt][half * 2 + q] * INV;
                        float t1 = __fadd_rn(g_esq[col], xs);
                        float d  = __fadd_rn(t1, -2.0f * a);
                        if (d < bd) { bd = d; bc = col; }
                    }
                }
                unsigned long long key =
                    ((unsigned long long)fkey(bd) << 32) | (unsigned)bc;
                unsigned long long o1 = __shfl_xor_sync(0xffffffffu, key, 1);
                if (o1 < key) key = o1;
                unsigned long long o2 = __shfl_xor_sync(0xffffffffu, key, 2);
                if (o2 < key) key = o2;
                if ((lane & 3) == 0) atomicMin(&g_best[row], key);
            }
        }
    } else if (EPI == 2) {
        // fused CE partials: per 64-col slab, (max, sum-exp) + label logit
        const int rq = lane >> 2;
#pragma unroll
        for (int mt = 0; mt < 4; mt++) {
#pragma unroll
            for (int half = 0; half < 2; half++) {
                int row = rowBase + warp_m * 64 + mt * 16 + rq + half * 8;
                int lab = g_labi[row];
                float mx = __int_as_float(0xff800000);
#pragma unroll
                for (int nt = 0; nt < 8; nt++)
#pragma unroll
                    for (int q = 0; q < 2; q++)
                        mx = fmaxf(mx, acc[mt][nt][half * 2 + q]);
                mx = fmaxf(mx, __shfl_xor_sync(0xffffffffu, mx, 1));
                mx = fmaxf(mx, __shfl_xor_sync(0xffffffffu, mx, 2));
                float s = 0.f;
#pragma unroll
                for (int nt = 0; nt < 8; nt++) {
#pragma unroll
                    for (int q = 0; q < 2; q++) {
                        float v = acc[mt][nt][half * 2 + q];
                        s += __expf(v - mx);
                        int col = colBase + warp_n * 64 + nt * 8 + (lane & 3) * 2 + q;
                        if (col == lab) g_labv[row] = v;
                    }
                }
                s += __shfl_xor_sync(0xffffffffu, s, 1);
                s += __shfl_xor_sync(0xffffffffu, s, 2);
                if ((lane & 3) == 0) {
                    int slab = blockIdx.x * 2 + warp_n;
                    g_pmax[(size_t)row * 16 + slab] = mx;
                    g_psum[(size_t)row * 16 + slab] = s;
                }
            }
        }
    } else {
#pragma unroll
        for (int mt = 0; mt < 4; mt++) {
#pragma unroll
            for (int nt = 0; nt < 8; nt++) {
                int row0 = rowBase + warp_m * 64 + mt * 16 + (lane >> 2);
                int col  = colBase + warp_n * 64 + nt * 8 + (lane & 3) * 2;
                *(float2*)(C + (size_t)row0 * ldc + col) =
                    make_float2(acc[mt][nt][0], acc[mt][nt][1]);
                *(float2*)(C + (size_t)(row0 + 8) * ldc + col) =
                    make_float2(acc[mt][nt][2], acc[mt][nt][3]);
            }
        }
    }
}

// ---------------- weight transpose + bf16 convert ---------------------------
__global__ void wconv_kernel(const float* __restrict__ W,
                             __nv_bfloat16* __restrict__ Wt, int N)
{
    __shared__ float tile[32][33];
    int k0 = blockIdx.y * 32, n0 = blockIdx.x * 32;
    int tx = threadIdx.x & 31, ty = threadIdx.x >> 5;
#pragma unroll
    for (int i = 0; i < 32; i += 8)
        tile[ty + i][tx] = W[(size_t)(k0 + ty + i) * N + n0 + tx];
    __syncthreads();
#pragma unroll
    for (int i = 0; i < 32; i += 8)
        Wt[(size_t)(n0 + ty + i) * 512 + k0 + tx] = __float2bfloat16(tile[tx][ty + i]);
}

// ---------------- VQ bookkeeping: count / scan / scatter / dw-sum -----------
__global__ void countk_kernel() {
    int row = blockIdx.x * 256 + threadIdx.x;
    int idx = (int)(unsigned)(g_best[row] & 0xFFFFFFFFull);
    atomicAdd(&g_cnti[idx], 1);
}

__global__ void prefix_kernel() {
    __shared__ int sh[MCODES];
    int t = threadIdx.x;
    int c = g_cnti[t];
    sh[t] = c;
    __syncthreads();
    for (int off = 1; off < MCODES; off <<= 1) {
        int add = (t >= off) ? sh[t - off] : 0;
        __syncthreads();
        sh[t] += add;
        __syncthreads();
    }
    g_off[t] = sh[t] - c;      // exclusive prefix
    g_counts[t] = (float)c;
}

__global__ void scatter_kernel() {
    int row = blockIdx.x * 256 + threadIdx.x;
    int idx = (int)(unsigned)(g_best[row] & 0xFFFFFFFFull);
    int p = atomicAdd(&g_fill[idx], 1);
    g_rows[g_off[idx] + p] = row;
}

// one block per code: sum assigned x rows, emit new_weight & new_embedding.
// NOTE: out_emb/out_w are offset by +1 float in the packed output buffer
// (4-byte aligned only) -> scalar stores, never float4.
__global__ void dwsum_kernel(const float* __restrict__ x,
                             const float* __restrict__ ema_wt,
                             float* __restrict__ out_emb,
                             float* __restrict__ out_w)
{
    int m = blockIdx.x, t = threadIdx.x;     // 128 threads x float4 = 512
    int beg = g_off[m], cnt = g_cnti[m];
    float4 a0 = make_float4(0.f, 0.f, 0.f, 0.f);
    float4 a1 = make_float4(0.f, 0.f, 0.f, 0.f);
    int j = 0;
    for (; j + 1 < cnt; j += 2) {
        int r0 = g_rows[beg + j], r1 = g_rows[beg + j + 1];
        float4 v0 = ((const float4*)(x + (size_t)r0 * DDIM))[t];
        float4 v1 = ((const float4*)(x + (size_t)r1 * DDIM))[t];
        a0.x += v0.x; a0.y += v0.y; a0.z += v0.z; a0.w += v0.w;
        a1.x += v1.x; a1.y += v1.y; a1.z += v1.z; a1.w += v1.w;
    }
    if (j < cnt) {
        int r0 = g_rows[beg + j];
        float4 v0 = ((const float4*)(x + (size_t)r0 * DDIM))[t];
        a0.x += v0.x; a0.y += v0.y; a0.z += v0.z; a0.w += v0.w;
    }
    a0.x += a1.x; a0.y += a1.y; a0.z += a1.z; a0.w += a1.w;
    float4 w = ((const float4*)(ema_wt + (size_t)m * DDIM))[t];
    float nc = g_newc[m];
    float nw0 = 0.999f * w.x + 0.001f * a0.x;
    float nw1 = 0.999f * w.y + 0.001f * a0.y;
    float nw2 = 0.999f * w.z + 0.001f * a0.z;
    float nw3 = 0.999f * w.w + 0.001f * a0.w;
    size_t ob = (size_t)m * DDIM + t * 4;
    out_w[ob + 0] = nw0;
    out_w[ob + 1] = nw1;
    out_w[ob + 2] = nw2;
    out_w[ob + 3] = nw3;
    out_emb[ob + 0] = nw0 / nc;
    out_emb[ob + 1] = nw1 / nc;
    out_emb[ob + 2] = nw2 / nc;
    out_emb[ob + 3] = nw3 / nc;
}

// ---------------- post-VQ: gather, quantized_st, vq loss ---------------------
__global__ void postvq_kernel(const float* __restrict__ x,
                              const float* __restrict__ emb,
                              float* __restrict__ out_q)
{
    int row = blockIdx.x;
    int idx = (int)(unsigned)(g_best[row] & 0xFFFFFFFFull);
    const float4* xr = (const float4*)(x   + (size_t)row * DDIM);
    const float4* er = (const float4*)(emb + (size_t)idx * DDIM);
    float4 xv = xr[threadIdx.x];
    float4 ev = er[threadIdx.x];
    float4 q;
    q.x = xv.x + (ev.x - xv.x);
    q.y = xv.y + (ev.y - xv.y);
    q.z = xv.z + (ev.z - xv.z);
    q.w = xv.w + (ev.w - xv.w);
    ((float4*)(out_q + (size_t)row * DDIM))[threadIdx.x] = q;

    float dx = xv.x - ev.x, dy = xv.y - ev.y, dz = xv.z - ev.z, dw2 = xv.w - ev.w;
    float s = dx * dx + dy * dy + dz * dz + dw2 * dw2;
    s = blockReduceSum(s);
    if (threadIdx.x == 0) g_vqrow[row] = 0.25f * s;
}

// ---------------- EMA count + perplexity ------------------------------------
__global__ void ema_kernel(const float* __restrict__ ema_count,
                           float* __restrict__ out_cnt,
                           float* __restrict__ out_perp)
{
    int m = threadIdx.x;
    float c = g_counts[m];
    float nc0 = 0.999f * ema_count[m] + 0.001f * c;
    float n = blockReduceSum(nc0);
    float newc = (nc0 + 1e-5f) / (n + (float)MCODES * 1e-5f) * n;
    out_cnt[m] = newc;
    g_newc[m] = newc;
    float p = c * (1.0f / (float)NROWS);
    float t = p * logf(p + 1e-10f);
    float s = blockReduceSum(t);
    if (m == 0) out_perp[0] = expf(-s);
}

// ---------------- LayerNorm + ReLU -> bf16 ----------------------------------
__global__ void ln_relu_bf16_kernel(const float* __restrict__ X,
                                    const float* __restrict__ g,
                                    const float* __restrict__ b,
                                    __nv_bfloat16* __restrict__ Y)
{
    constexpr int W = 512;
    constexpr int PER = 2;
    int row = blockIdx.x;
    const float* x = X + (size_t)row * W;
    float v[PER];
    float s = 0.f;
#pragma unroll
    for (int i = 0; i < PER; i++) { v[i] = x[threadIdx.x + i * 256]; s += v[i]; }
    float mean = blockReduceSum(s) * (1.0f / W);
    float s2 = 0.f;
#pragma unroll
    for (int i = 0; i < PER; i++) { float d = v[i] - mean; s2 += d * d; }
    float var = blockReduceSum(s2) * (1.0f / W);
    float rstd = rsqrtf(var + 1e-5f);
#pragma unroll
    for (int i = 0; i < PER; i++) {
        int c = threadIdx.x + i * 256;
        float o = (v[i] - mean) * rstd * g[c] + b[c];
        Y[(size_t)row * W + c] = __float2bfloat16(fmaxf(o, 0.f));
    }
}

// ---------------- dtype detection + label convert ---------------------------
__global__ void detect_mask_kernel(const unsigned* __restrict__ m) {
    __shared__ int bad, gt1;
    if (threadIdx.x == 0) { bad = 0; gt1 = 0; }
    __syncthreads();
    for (int i = threadIdx.x; i < 8192; i += blockDim.x) {
        unsigned v = m[i];
        if (v > 1u) {
            atomicOr(&gt1, 1);
            if (v != 0x3F800000u) atomicOr(&bad, 1);
        }
    }
    __syncthreads();
    if (threadIdx.x == 0) g_mask_mode = (gt1 == 0) ? 0 : (bad ? 2 : 1);
}

__global__ void detect_lab_kernel(const unsigned* __restrict__ lab) {
    __shared__ int any_nz;
    if (threadIdx.x == 0) any_nz = 0;
    __syncthreads();
    for (int i = threadIdx.x; i < NROWS / 2; i += blockDim.x) {
        if (lab[2 * i + 1] != 0u) atomicOr(&any_nz, 1);
    }
    __syncthreads();
    if (threadIdx.x == 0) g_lab_mode = any_nz ? 0 : 1;
}

__global__ void labconv_kernel(const void* __restrict__ labels) {
    int i = blockIdx.x * 256 + threadIdx.x;
    g_labi[i] = g_lab_mode ? (int)((const long long*)labels)[i]
                           : ((const int*)labels)[i];
}

// ---------------- CE combine + final loss ------------------------------------
__global__ void ce_combine_kernel(const void* __restrict__ mask,
                                  float* __restrict__ out_loss)
{
    int row = blockIdx.x * 256 + threadIdx.x;
    const float* pm = g_pmax + (size_t)row * 16;
    const float* ps = g_psum + (size_t)row * 16;
    float M = __int_as_float(0xff800000);
#pragma unroll
    for (int i = 0; i < 16; i++) M = fmaxf(M, pm[i]);
    float S = 0.f;
#pragma unroll
    for (int i = 0; i < 16; i++) S += ps[i] * expf(pm[i] - M);
    float lse = M + logf(S);
    int mode = g_mask_mode;
    bool invalid;
    if (mode == 2)      invalid = ((const unsigned char*)mask)[row] != 0;
    else if (mode == 1) invalid = ((const float*)mask)[row] != 0.f;
    else                invalid = ((const int*)mask)[row] != 0;
    float ce = invalid ? 0.f : (lse - g_labv[row]);
    out_loss[row] = ce + g_vqrow[row];
}

// ---------------- launch -----------------------------------------------------
extern "C" void kernel_launch(void* const* d_in, const int* in_sizes, int n_in,
                              void* d_out, int out_size)
{
    const float* x         = (const float*)d_in[0];
    const void*  mask      = d_in[1];
    const void*  labels    = d_in[2];
    const float* emb       = (const float*)d_in[3];
    const float* ema_count = (const float*)d_in[4];
    const float* ema_wt    = (const float*)d_in[5];
    const float* ln1g      = (const float*)d_in[6];
    const float* ln1b      = (const float*)d_in[7];
    const float* W1        = (const float*)d_in[8];
    const float* ln2g      = (const float*)d_in[9];
    const float* ln2b      = (const float*)d_in[10];
    const float* W2        = (const float*)d_in[11];

    float* out      = (float*)d_out;
    float* out_q    = out;
    float* out_loss = out + (size_t)NROWS * DDIM;
    float* out_perp = out_loss + NROWS;
    float* out_emb  = out_perp + 1;
    float* out_cnt  = out_emb + (size_t)MCODES * DDIM;
    float* out_w    = out_cnt + MCODES;

    void *pa1, *ph, *pa2, *pxsq, *pesq, *pw1t, *pw2t, *pxs, *pes;
    cudaGetSymbolAddress(&pa1, g_a1b);
    cudaGetSymbolAddress(&ph, g_h);
    cudaGetSymbolAddress(&pa2, g_a2b);
    cudaGetSymbolAddress(&pxsq, g_xsq);
    cudaGetSymbolAddress(&pesq, g_esq);
    cudaGetSymbolAddress(&pw1t, g_w1t);
    cudaGetSymbolAddress(&pw2t, g_w2t);
    cudaGetSymbolAddress(&pxs, g_xs);
    cudaGetSymbolAddress(&pes, g_es);

    // --- VQ path: bucket-exact argmin on tensor cores (fp16 3-term split) ---
    init_kernel<<<128, 256>>>();
    seqsq_kernel<<<MCODES, 128>>>(emb, (float*)pesq);
    seqsq_kernel<<<NROWS, 128>>>(x, (float*)pxsq);
    split2_kernel<<<NROWS / 2, 256>>>((const float4*)x, (__half*)pxs, 16.0f);
    split2_kernel<<<MCODES / 2, 256>>>((const float4*)emb, (__half*)pes, 4096.0f);
    tcg256_kernel<3, 1, true><<<dim3(MCODES / 128, NROWS / 256), 256>>>(
        (const uint16_t*)pxs, 1024, (const uint16_t*)pes, 1024, nullptr, 0);

    // --- VQ bookkeeping: counts -> scan -> ema -> scatter -> dw/emb ---
    countk_kernel<<<NROWS / 256, 256>>>();
    prefix_kernel<<<1, MCODES>>>();
    ema_kernel<<<1, MCODES>>>(ema_count, out_cnt, out_perp);
    scatter_kernel<<<NROWS / 256, 256>>>();
    dwsum_kernel<<<MCODES, 128>>>(x, ema_wt, out_emb, out_w);
    postvq_kernel<<<NROWS, 128>>>(x, emb, out_q);

    // --- decoder path: bf16 tensor-core GEMMs (double-buffered) ---
    wconv_kernel<<<dim3(HDIM / 32, DDIM / 32), 256>>>(W1, (__nv_bfloat16*)pw1t, HDIM);
    wconv_kernel<<<dim3(MCODES / 32, HDIM / 32), 256>>>(W2, (__nv_bfloat16*)pw2t, MCODES);
    ln_relu_bf16_kernel<<<NROWS, 256>>>(x, ln1g, ln1b, (__nv_bfloat16*)pa1);
    tcg256_kernel<1, 0, false><<<dim3(HDIM / 128, NROWS / 256), 256>>>(
        (const uint16_t*)pa1, 512, (const uint16_t*)pw1t, 512, (float*)ph, HDIM);
    ln_relu_bf16_kernel<<<NROWS, 256>>>((const float*)ph, ln2g, ln2b, (__nv_bfloat16*)pa2);

    // --- W2 GEMM with fused CE partials, then combine ---
    detect_mask_kernel<<<1, 256>>>((const unsigned*)mask);
    detect_lab_kernel<<<1, 256>>>((const unsigned*)labels);
    labconv_kernel<<<NROWS / 256, 256>>>(labels);
    tcg256_kernel<1, 2, false><<<dim3(MCODES / 128, NROWS / 256), 256>>>(
        (const uint16_t*)pa2, 512, (const uint16_t*)pw2t, 512, nullptr, 0);
    ce_combine_kernel<<<NROWS / 256, 256>>>(mask, out_loss);
}

// round 11
// speedup vs baseline: 2.9682x; 1.0073x over previous
#include <cuda_runtime.h>
#include <cuda_bf16.h>
#include <cuda_fp16.h>
#include <cstdint>

#define NROWS 32768   // B*T
#define DDIM  512
#define HDIM  512
#define MCODES 1024

// ---------------- scratch (static device allocations; no cudaMalloc) -------
__device__ unsigned long long g_best[NROWS];
__device__ float g_counts[MCODES];
__device__ float g_esq[MCODES];
__device__ float g_xsq[NROWS];
__device__ float g_vqrow[NROWS];
__device__ float g_newc[MCODES];
__device__ int   g_mask_mode;
__device__ int   g_lab_mode;     // 0 = int32, 1 = int64
__device__ int   g_labi[NROWS];
__device__ int   g_cnti[MCODES];
__device__ int   g_off[MCODES];
__device__ int   g_fill[MCODES];
__device__ int   g_rows[NROWS];
__device__ float g_pmax[(size_t)NROWS * 16];
__device__ float g_psum[(size_t)NROWS * 16];
__device__ float g_labv[NROWS];
__device__ __align__(16) __half g_xs[(size_t)NROWS * 1024];    // 16*x 2-way fp16 split
__device__ __align__(16) __half g_es[(size_t)MCODES * 1024];   // 4096*e 2-way fp16 split
__device__ __align__(16) __nv_bfloat16 g_a1b[(size_t)NROWS * DDIM];
__device__ __align__(16) __nv_bfloat16 g_a2b[(size_t)NROWS * HDIM];
__device__ __align__(16) __nv_bfloat16 g_hb[(size_t)NROWS * HDIM];     // h in bf16
__device__ __align__(16) __nv_bfloat16 g_w1t[(size_t)HDIM * DDIM];     // [N=512, K=512]
__device__ __align__(16) __nv_bfloat16 g_w2t[(size_t)MCODES * HDIM];   // [N=1024, K=512]

// ---------------- reduction helpers ----------------------------------------
__device__ __forceinline__ float warpReduceSum(float v) {
#pragma unroll
    for (int o = 16; o > 0; o >>= 1) v += __shfl_down_sync(0xffffffffu, v, o);
    return v;
}
__device__ __forceinline__ float blockReduceSum(float v) {
    __shared__ float s[32];
    __syncthreads();
    v = warpReduceSum(v);
    int lane = threadIdx.x & 31, w = threadIdx.x >> 5;
    if (lane == 0) s[w] = v;
    __syncthreads();
    int nw = blockDim.x >> 5;
    float r = (threadIdx.x < nw) ? s[threadIdx.x] : 0.f;
    if (w == 0) { r = warpReduceSum(r); if (lane == 0) s[0] = r; }
    __syncthreads();
    return s[0];
}
__device__ __forceinline__ unsigned fkey(float f) {
    unsigned u = __float_as_uint(f);
    return (u & 0x80000000u) ? ~u : (u | 0x80000000u);
}
__device__ __forceinline__ uint32_t smem_addr_u32(const void* p) {
    return (uint32_t)__cvta_generic_to_shared(p);
}

// ---------------- init ------------------------------------------------------
__global__ void init_kernel() {
    int i = blockIdx.x * blockDim.x + threadIdx.x;   // grid covers 32768
    g_best[i] = ~0ull;
    if (i < MCODES) { g_cnti[i] = 0; g_fill[i] = 0; }
}

// Strict sequential fp32 sum of squares per row (reference rounding order).
__global__ void seqsq_kernel(const float* __restrict__ X, float* __restrict__ out) {
    __shared__ float row[DDIM];
    const float4* src = (const float4*)(X + (size_t)blockIdx.x * DDIM);
    ((float4*)row)[threadIdx.x] = src[threadIdx.x];
    __syncthreads();
    if (threadIdx.x == 0) {
        float s = 0.f;
#pragma unroll 8
        for (int i = 0; i < DDIM; i++)
            s = __fadd_rn(s, __fmul_rn(row[i], row[i]));
        out[blockIdx.x] = s;
    }
}

// 2-way fp16 split of scale*v, vectorized: 4 elems per thread
__global__ void split2_kernel(const float4* __restrict__ V,
                              __half* __restrict__ S, float scale)
{
    int i = blockIdx.x * 256 + threadIdx.x;          // over nrows*128
    int row = i >> 7, c4 = i & 127;
    float4 v = V[i];
    struct __align__(8) H4 { __half h[4]; } h0, h1;
    float vv[4] = {v.x * scale, v.y * scale, v.z * scale, v.w * scale};
#pragma unroll
    for (int k = 0; k < 4; k++) {
        __half a = __float2half_rn(vv[k]);
        h0.h[k] = a;
        h1.h[k] = __float2half_rn(vv[k] - __half2float(a));
    }
    size_t base = (size_t)row * 1024 + c4 * 4;
    *(uint2*)(S + base)       = *(uint2*)&h0;
    *(uint2*)(S + base + 512) = *(uint2*)&h1;
}

// ---------------- mma / cp.async helpers ------------------------------------
template<bool USE_HALF>
__device__ __forceinline__ void mma16816t(float* d, const uint32_t* a,
                                          const uint32_t* b) {
    if (USE_HALF)
        asm volatile(
            "mma.sync.aligned.m16n8k16.row.col.f32.f16.f16.f32 "
            "{%0,%1,%2,%3}, {%4,%5,%6,%7}, {%8,%9}, {%0,%1,%2,%3};"
            : "+f"(d[0]), "+f"(d[1]), "+f"(d[2]), "+f"(d[3])
            : "r"(a[0]), "r"(a[1]), "r"(a[2]), "r"(a[3]), "r"(b[0]), "r"(b[1]));
    else
        asm volatile(
            "mma.sync.aligned.m16n8k16.row.col.f32.bf16.bf16.f32 "
            "{%0,%1,%2,%3}, {%4,%5,%6,%7}, {%8,%9}, {%0,%1,%2,%3};"
            : "+f"(d[0]), "+f"(d[1]), "+f"(d[2]), "+f"(d[3])
            : "r"(a[0]), "r"(a[1]), "r"(a[2]), "r"(a[3]), "r"(b[0]), "r"(b[1]));
}

__device__ __forceinline__ void cpasync16(uint32_t dst, const void* src) {
    asm volatile("cp.async.cg.shared.global [%0], [%1], 16;"
                 :: "r"(dst), "l"(src) : "memory");
}

__device__ __forceinline__ uint32_t swoff(int r, int c) {
    return ((uint32_t)(r >> 1) << 7) |
           ((uint32_t)((((r & 1) << 2) | c) ^ ((r >> 1) & 7)) << 4);
}

#define STAGE_BYTES 24576u

template<int NSEG>
__device__ __forceinline__ void tcg_load(
    const uint16_t* A, int ldA, const uint16_t* B, int ldB,
    int rowBase, int colBase, uint32_t sbase, int st, int it, int tid)
{
    int seg = it >> 4, kk = (it & 15) * 32;
    int sa = 0, sb = 0;
    if (NSEG == 3) { sa = (seg == 2) ? 512 : 0; sb = (seg == 1) ? 512 : 0; }
    uint32_t base = sbase + (uint32_t)st * STAGE_BYTES;
#pragma unroll
    for (int j = 0; j < 4; j++) {          // A: 256 rows x 4 chunks
        int ch = tid + j * 256, r = ch >> 2, c = ch & 3;
        cpasync16(base + swoff(r, c),
                  A + (size_t)(rowBase + r) * ldA + sa + kk + c * 8);
    }
#pragma unroll
    for (int j = 0; j < 2; j++) {          // B: 128 rows x 4 chunks
        int ch = tid + j * 256, r = ch >> 2, c = ch & 3;
        cpasync16(base + 16384 + swoff(r, c),
                  B + (size_t)(colBase + r) * ldB + sb + kk + c * 8);
    }
    asm volatile("cp.async.commit_group;" ::: "memory");
}

// ---------------- 256x128 4-stage-pipelined tensor-core GEMM ----------------
// EPI: 0 = store fp32 C, 1 = fused bucket-argmin (acc scaled 2^16),
//      2 = fused CE partials, 3 = store bf16 C.
template<int NSEG, int EPI, bool USE_HALF>
__global__ void __launch_bounds__(256) tcg256_kernel(
    const uint16_t* __restrict__ A, int ldA,
    const uint16_t* __restrict__ B, int ldB,
    float* __restrict__ C, int ldc)
{
    extern __shared__ __align__(16) unsigned char smem_s[];   // 4 x 24KB
    const int tid = threadIdx.x, lane = tid & 31, wid = tid >> 5;
    const int warp_m = wid & 3, warp_n = wid >> 2;   // 4m x 2n warps
    const int rowBase = blockIdx.y * 256;
    const int colBase = blockIdx.x * 128;
    const uint32_t sbase = smem_addr_u32(smem_s);

    float acc[4][8][4];
#pragma unroll
    for (int i = 0; i < 4; i++)
#pragma unroll
        for (int j = 0; j < 8; j++)
#pragma unroll
            for (int q = 0; q < 4; q++) acc[i][j][q] = 0.f;

    uint32_t offA[4][2], offB[4][2];
#pragma unroll
    for (int mt = 0; mt < 4; mt++) {
        int r = warp_m * 64 + mt * 16 + (lane & 15);
#pragma unroll
        for (int ks = 0; ks < 2; ks++)
            offA[mt][ks] = swoff(r, ks * 2 + (lane >> 4));
    }
#pragma unroll
    for (int p = 0; p < 4; p++) {
        int r = warp_n * 64 + p * 16 + (lane & 15);
#pragma unroll
        for (int ks = 0; ks < 2; ks++)
            offB[p][ks] = 16384u + swoff(r, ks * 2 + (lane >> 4));
    }

    const int nch = NSEG * 16;
    tcg_load<NSEG>(A, ldA, B, ldB, rowBase, colBase, sbase, 0, 0, tid);
    tcg_load<NSEG>(A, ldA, B, ldB, rowBase, colBase, sbase, 1, 1, tid);
    tcg_load<NSEG>(A, ldA, B, ldB, rowBase, colBase, sbase, 2, 2, tid);

#pragma unroll 1
    for (int i = 0; i < nch; i++) {
        int rem = nch - 1 - i;
        if (rem >= 2)      asm volatile("cp.async.wait_group 2;" ::: "memory");
        else if (rem == 1) asm volatile("cp.async.wait_group 1;" ::: "memory");
        else               asm volatile("cp.async.wait_group 0;" ::: "memory");
        __syncthreads();
        if (i + 3 < nch)
            tcg_load<NSEG>(A, ldA, B, ldB, rowBase, colBase, sbase,
                           (i + 3) & 3, i + 3, tid);

        uint32_t stB = sbase + (uint32_t)(i & 3) * STAGE_BYTES;
#pragma unroll
        for (int ks = 0; ks < 2; ks++) {
            uint32_t af[4][4];
#pragma unroll
            for (int mt = 0; mt < 4; mt++) {
                uint32_t ad = stB + offA[mt][ks];
                asm volatile("ldmatrix.sync.aligned.m8n8.x4.shared.b16 {%0,%1,%2,%3}, [%4];"
                             : "=r"(af[mt][0]), "=r"(af[mt][1]),
                               "=r"(af[mt][2]), "=r"(af[mt][3]) : "r"(ad));
            }
            uint32_t bf[8][2];
#pragma unroll
            for (int p = 0; p < 4; p++) {
                uint32_t bd = stB + offB[p][ks];
                uint32_t q0, q1, q2, q3;
                asm volatile("ldmatrix.sync.aligned.m8n8.x4.shared.b16 {%0,%1,%2,%3}, [%4];"
                             : "=r"(q0), "=r"(q1), "=r"(q2), "=r"(q3) : "r"(bd));
                bf[2 * p][0] = q0; bf[2 * p][1] = q2;
                bf[2 * p + 1][0] = q1; bf[2 * p + 1][1] = q3;
            }
#pragma unroll
            for (int mt = 0; mt < 4; mt++)
#pragma unroll
                for (int nt = 0; nt < 8; nt++)
                    mma16816t<USE_HALF>(acc[mt][nt], af[mt], bf[nt]);
        }
    }

    if (EPI == 1) {
        // acc holds 65536 * (x . e); d = fl(fl(esq+xsq) - 2*(acc/65536))
        const float INV = 1.0f / 65536.0f;
        const int rq = lane >> 2;
#pragma unroll
        for (int mt = 0; mt < 4; mt++) {
#pragma unroll
            for (int half = 0; half < 2; half++) {
                int row = rowBase + warp_m * 64 + mt * 16 + rq + half * 8;
                float xs = g_xsq[row];
                float bd = __int_as_float(0x7f800000);
                int bc = 0;
#pragma unroll
                for (int nt = 0; nt < 8; nt++) {
#pragma unroll
                    for (int q = 0; q < 2; q++) {
                        int col = colBase + warp_n * 64 + nt * 8 + (lane & 3) * 2 + q;
                        float a = acc[mt][nt][half * 2 + q] * INV;
                        float t1 = __fadd_rn(g_esq[col], xs);
                        float d  = __fadd_rn(t1, -2.0f * a);
                        if (d < bd) { bd = d; bc = col; }
                    }
                }
                unsigned long long key =
                    ((unsigned long long)fkey(bd) << 32) | (unsigned)bc;
                unsigned long long o1 = __shfl_xor_sync(0xffffffffu, key, 1);
                if (o1 < key) key = o1;
                unsigned long long o2 = __shfl_xor_sync(0xffffffffu, key, 2);
                if (o2 < key) key = o2;
                if ((lane & 3) == 0) atomicMin(&g_best[row], key);
            }
        }
    } else if (EPI == 2) {
        // fused CE partials: per 64-col slab, (max, sum-exp) + label logit
        const int rq = lane >> 2;
#pragma unroll
        for (int mt = 0; mt < 4; mt++) {
#pragma unroll
            for (int half = 0; half < 2; half++) {
                int row = rowBase + warp_m * 64 + mt * 16 + rq + half * 8;
                int lab = g_labi[row];
                float mx = __int_as_float(0xff800000);
#pragma unroll
                for (int nt = 0; nt < 8; nt++)
#pragma unroll
                    for (int q = 0; q < 2; q++)
                        mx = fmaxf(mx, acc[mt][nt][half * 2 + q]);
                mx = fmaxf(mx, __shfl_xor_sync(0xffffffffu, mx, 1));
                mx = fmaxf(mx, __shfl_xor_sync(0xffffffffu, mx, 2));
                float s = 0.f;
#pragma unroll
                for (int nt = 0; nt < 8; nt++) {
#pragma unroll
                    for (int q = 0; q < 2; q++) {
                        float v = acc[mt][nt][half * 2 + q];
                        s += __expf(v - mx);
                        int col = colBase + warp_n * 64 + nt * 8 + (lane & 3) * 2 + q;
                        if (col == lab) g_labv[row] = v;
                    }
                }
                s += __shfl_xor_sync(0xffffffffu, s, 1);
                s += __shfl_xor_sync(0xffffffffu, s, 2);
                if ((lane & 3) == 0) {
                    int slab = blockIdx.x * 2 + warp_n;
                    g_pmax[(size_t)row * 16 + slab] = mx;
                    g_psum[(size_t)row * 16 + slab] = s;
                }
            }
        }
    } else if (EPI == 3) {
        __nv_bfloat16* Cb = (__nv_bfloat16*)C;
#pragma unroll
        for (int mt = 0; mt < 4; mt++) {
#pragma unroll
            for (int nt = 0; nt < 8; nt++) {
                int row0 = rowBase + warp_m * 64 + mt * 16 + (lane >> 2);
                int col  = colBase + warp_n * 64 + nt * 8 + (lane & 3) * 2;
                __nv_bfloat162 v0, v1;
                v0.x = __float2bfloat16(acc[mt][nt][0]);
                v0.y = __float2bfloat16(acc[mt][nt][1]);
                v1.x = __float2bfloat16(acc[mt][nt][2]);
                v1.y = __float2bfloat16(acc[mt][nt][3]);
                *(__nv_bfloat162*)(Cb + (size_t)row0 * ldc + col) = v0;
                *(__nv_bfloat162*)(Cb + (size_t)(row0 + 8) * ldc + col) = v1;
            }
        }
    } else {
#pragma unroll
        for (int mt = 0; mt < 4; mt++) {
#pragma unroll
            for (int nt = 0; nt < 8; nt++) {
                int row0 = rowBase + warp_m * 64 + mt * 16 + (lane >> 2);
                int col  = colBase + warp_n * 64 + nt * 8 + (lane & 3) * 2;
                *(float2*)(C + (size_t)row0 * ldc + col) =
                    make_float2(acc[mt][nt][0], acc[mt][nt][1]);
                *(float2*)(C + (size_t)(row0 + 8) * ldc + col) =
                    make_float2(acc[mt][nt][2], acc[mt][nt][3]);
            }
        }
    }
}

// ---------------- weight transpose + bf16 convert ---------------------------
__global__ void wconv_kernel(const float* __restrict__ W,
                             __nv_bfloat16* __restrict__ Wt, int N)
{
    __shared__ float tile[32][33];
    int k0 = blockIdx.y * 32, n0 = blockIdx.x * 32;
    int tx = threadIdx.x & 31, ty = threadIdx.x >> 5;
#pragma unroll
    for (int i = 0; i < 32; i += 8)
        tile[ty + i][tx] = W[(size_t)(k0 + ty + i) * N + n0 + tx];
    __syncthreads();
#pragma unroll
    for (int i = 0; i < 32; i += 8)
        Wt[(size_t)(n0 + ty + i) * 512 + k0 + tx] = __float2bfloat16(tile[tx][ty + i]);
}

// ---------------- VQ bookkeeping: count / scan / scatter / dw-sum -----------
__global__ void countk_kernel() {
    int row = blockIdx.x * 256 + threadIdx.x;
    int idx = (int)(unsigned)(g_best[row] & 0xFFFFFFFFull);
    atomicAdd(&g_cnti[idx], 1);
}

__global__ void prefix_kernel() {
    __shared__ int sh[MCODES];
    int t = threadIdx.x;
    int c = g_cnti[t];
    sh[t] = c;
    __syncthreads();
    for (int off = 1; off < MCODES; off <<= 1) {
        int add = (t >= off) ? sh[t - off] : 0;
        __syncthreads();
        sh[t] += add;
        __syncthreads();
    }
    g_off[t] = sh[t] - c;      // exclusive prefix
    g_counts[t] = (float)c;
}

__global__ void scatter_kernel() {
    int row = blockIdx.x * 256 + threadIdx.x;
    int idx = (int)(unsigned)(g_best[row] & 0xFFFFFFFFull);
    int p = atomicAdd(&g_fill[idx], 1);
    g_rows[g_off[idx] + p] = row;
}

// one block per code: sum assigned x rows, emit new_weight & new_embedding.
// out_emb/out_w are +1-float offset in packed output (4B aligned) -> scalar stores.
__global__ void dwsum_kernel(const float* __restrict__ x,
                             const float* __restrict__ ema_wt,
                             float* __restrict__ out_emb,
                             float* __restrict__ out_w)
{
    int m = blockIdx.x, t = threadIdx.x;     // 128 threads x float4 = 512
    int beg = g_off[m], cnt = g_cnti[m];
    float4 a0 = make_float4(0.f, 0.f, 0.f, 0.f);
    float4 a1 = make_float4(0.f, 0.f, 0.f, 0.f);
    int j = 0;
    for (; j + 1 < cnt; j += 2) {
        int r0 = g_rows[beg + j], r1 = g_rows[beg + j + 1];
        float4 v0 = ((const float4*)(x + (size_t)r0 * DDIM))[t];
        float4 v1 = ((const float4*)(x + (size_t)r1 * DDIM))[t];
        a0.x += v0.x; a0.y += v0.y; a0.z += v0.z; a0.w += v0.w;
        a1.x += v1.x; a1.y += v1.y; a1.z += v1.z; a1.w += v1.w;
    }
    if (j < cnt) {
        int r0 = g_rows[beg + j];
        float4 v0 = ((const float4*)(x + (size_t)r0 * DDIM))[t];
        a0.x += v0.x; a0.y += v0.y; a0.z += v0.z; a0.w += v0.w;
    }
    a0.x += a1.x; a0.y += a1.y; a0.z += a1.z; a0.w += a1.w;
    float4 w = ((const float4*)(ema_wt + (size_t)m * DDIM))[t];
    float nc = g_newc[m];
    float nw0 = 0.999f * w.x + 0.001f * a0.x;
    float nw1 = 0.999f * w.y + 0.001f * a0.y;
    float nw2 = 0.999f * w.z + 0.001f * a0.z;
    float nw3 = 0.999f * w.w + 0.001f * a0.w;
    size_t ob = (size_t)m * DDIM + t * 4;
    out_w[ob + 0] = nw0;
    out_w[ob + 1] = nw1;
    out_w[ob + 2] = nw2;
    out_w[ob + 3] = nw3;
    out_emb[ob + 0] = nw0 / nc;
    out_emb[ob + 1] = nw1 / nc;
    out_emb[ob + 2] = nw2 / nc;
    out_emb[ob + 3] = nw3 / nc;
}

// ---------------- post-VQ: gather, quantized_st, vq loss ---------------------
__global__ void postvq_kernel(const float* __restrict__ x,
                              const float* __restrict__ emb,
                              float* __restrict__ out_q)
{
    int row = blockIdx.x;
    int idx = (int)(unsigned)(g_best[row] & 0xFFFFFFFFull);
    const float4* xr = (const float4*)(x   + (size_t)row * DDIM);
    const float4* er = (const float4*)(emb + (size_t)idx * DDIM);
    float4 xv = xr[threadIdx.x];
    float4 ev = er[threadIdx.x];
    float4 q;
    q.x = xv.x + (ev.x - xv.x);
    q.y = xv.y + (ev.y - xv.y);
    q.z = xv.z + (ev.z - xv.z);
    q.w = xv.w + (ev.w - xv.w);
    ((float4*)(out_q + (size_t)row * DDIM))[threadIdx.x] = q;

    float dx = xv.x - ev.x, dy = xv.y - ev.y, dz = xv.z - ev.z, dw2 = xv.w - ev.w;
    float s = dx * dx + dy * dy + dz * dz + dw2 * dw2;
    s = blockReduceSum(s);
    if (threadIdx.x == 0) g_vqrow[row] = 0.25f * s;
}

// ---------------- EMA count + perplexity ------------------------------------
__global__ void ema_kernel(const float* __restrict__ ema_count,
                           float* __restrict__ out_cnt,
                           float* __restrict__ out_perp)
{
    int m = threadIdx.x;
    float c = g_counts[m];
    float nc0 = 0.999f * ema_count[m] + 0.001f * c;
    float n = blockReduceSum(nc0);
    float newc = (nc0 + 1e-5f) / (n + (float)MCODES * 1e-5f) * n;
    out_cnt[m] = newc;
    g_newc[m] = newc;
    float p = c * (1.0f / (float)NROWS);
    float t = p * logf(p + 1e-10f);
    float s = blockReduceSum(t);
    if (m == 0) out_perp[0] = expf(-s);
}

// ---------------- LayerNorm + ReLU -> bf16 (templated input) ----------------
template<typename T>
__global__ void ln_relu_kernel(const T* __restrict__ X,
                               const float* __restrict__ g,
                               const float* __restrict__ b,
                               __nv_bfloat16* __restrict__ Y)
{
    constexpr int W = 512;
    constexpr int PER = 2;
    int row = blockIdx.x;
    const T* x = X + (size_t)row * W;
    float v[PER];
    float s = 0.f;
#pragma unroll
    for (int i = 0; i < PER; i++) { v[i] = (float)x[threadIdx.x + i * 256]; s += v[i]; }
    float mean = blockReduceSum(s) * (1.0f / W);
    float s2 = 0.f;
#pragma unroll
    for (int i = 0; i < PER; i++) { float d = v[i] - mean; s2 += d * d; }
    float var = blockReduceSum(s2) * (1.0f / W);
    float rstd = rsqrtf(var + 1e-5f);
#pragma unroll
    for (int i = 0; i < PER; i++) {
        int c = threadIdx.x + i * 256;
        float o = (v[i] - mean) * rstd * g[c] + b[c];
        Y[(size_t)row * W + c] = __float2bfloat16(fmaxf(o, 0.f));
    }
}

// ---------------- dtype detection + label convert ---------------------------
__global__ void detect_mask_kernel(const unsigned* __restrict__ m) {
    __shared__ int bad, gt1;
    if (threadIdx.x == 0) { bad = 0; gt1 = 0; }
    __syncthreads();
    for (int i = threadIdx.x; i < 8192; i += blockDim.x) {
        unsigned v = m[i];
        if (v > 1u) {
            atomicOr(&gt1, 1);
            if (v != 0x3F800000u) atomicOr(&bad, 1);
        }
    }
    __syncthreads();
    if (threadIdx.x == 0) g_mask_mode = (gt1 == 0) ? 0 : (bad ? 2 : 1);
}

__global__ void detect_lab_kernel(const unsigned* __restrict__ lab) {
    __shared__ int any_nz;
    if (threadIdx.x == 0) any_nz = 0;
    __syncthreads();
    for (int i = threadIdx.x; i < NROWS / 2; i += blockDim.x) {
        if (lab[2 * i + 1] != 0u) atomicOr(&any_nz, 1);
    }
    __syncthreads();
    if (threadIdx.x == 0) g_lab_mode = any_nz ? 0 : 1;
}

__global__ void labconv_kernel(const void* __restrict__ labels) {
    int i = blockIdx.x * 256 + threadIdx.x;
    g_labi[i] = g_lab_mode ? (int)((const long long*)labels)[i]
                           : ((const int*)labels)[i];
}

// ---------------- CE combine + final loss ------------------------------------
__global__ void ce_combine_kernel(const void* __restrict__ mask,
                                  float* __restrict__ out_loss)
{
    int row = blockIdx.x * 256 + threadIdx.x;
    const float* pm = g_pmax + (size_t)row * 16;
    const float* ps = g_psum + (size_t)row * 16;
    float M = __int_as_float(0xff800000);
#pragma unroll
    for (int i = 0; i < 16; i++) M = fmaxf(M, pm[i]);
    float S = 0.f;
#pragma unroll
    for (int i = 0; i < 16; i++) S += ps[i] * expf(pm[i] - M);
    float lse = M + logf(S);
    int mode = g_mask_mode;
    bool invalid;
    if (mode == 2)      invalid = ((const unsigned char*)mask)[row] != 0;
    else if (mode == 1) invalid = ((const float*)mask)[row] != 0.f;
    else                invalid = ((const int*)mask)[row] != 0;
    float ce = invalid ? 0.f : (lse - g_labv[row]);
    out_loss[row] = ce + g_vqrow[row];
}

// ---------------- launch -----------------------------------------------------
extern "C" void kernel_launch(void* const* d_in, const int* in_sizes, int n_in,
                              void* d_out, int out_size)
{
    const float* x         = (const float*)d_in[0];
    const void*  mask      = d_in[1];
    const void*  labels    = d_in[2];
    const float* emb       = (const float*)d_in[3];
    const float* ema_count = (const float*)d_in[4];
    const float* ema_wt    = (const float*)d_in[5];
    const float* ln1g      = (const float*)d_in[6];
    const float* ln1b      = (const float*)d_in[7];
    const float* W1        = (const float*)d_in[8];
    const float* ln2g      = (const float*)d_in[9];
    const float* ln2b      = (const float*)d_in[10];
    const float* W2        = (const float*)d_in[11];

    float* out      = (float*)d_out;
    float* out_q    = out;
    float* out_loss = out + (size_t)NROWS * DDIM;
    float* out_perp = out_loss + NROWS;
    float* out_emb  = out_perp + 1;
    float* out_cnt  = out_emb + (size_t)MCODES * DDIM;
    float* out_w    = out_cnt + MCODES;

    void *pa1, *phb, *pa2, *pxsq, *pesq, *pw1t, *pw2t, *pxs, *pes;
    cudaGetSymbolAddress(&pa1, g_a1b);
    cudaGetSymbolAddress(&phb, g_hb);
    cudaGetSymbolAddress(&pa2, g_a2b);
    cudaGetSymbolAddress(&pxsq, g_xsq);
    cudaGetSymbolAddress(&pesq, g_esq);
    cudaGetSymbolAddress(&pw1t, g_w1t);
    cudaGetSymbolAddress(&pw2t, g_w2t);
    cudaGetSymbolAddress(&pxs, g_xs);
    cudaGetSymbolAddress(&pes, g_es);

    const int SMEM = 4 * 24576;   // 96 KB dynamic
    cudaFuncSetAttribute(tcg256_kernel<3, 1, true>,
                         cudaFuncAttributeMaxDynamicSharedMemorySize, SMEM);
    cudaFuncSetAttribute(tcg256_kernel<1, 3, false>,
                         cudaFuncAttributeMaxDynamicSharedMemorySize, SMEM);
    cudaFuncSetAttribute(tcg256_kernel<1, 2, false>,
                         cudaFuncAttributeMaxDynamicSharedMemorySize, SMEM);

    // --- VQ path: bucket-exact argmin on tensor cores (fp16 3-term split) ---
    init_kernel<<<128, 256>>>();
    seqsq_kernel<<<MCODES, 128>>>(emb, (float*)pesq);
    seqsq_kernel<<<NROWS, 128>>>(x, (float*)pxsq);
    split2_kernel<<<NROWS / 2, 256>>>((const float4*)x, (__half*)pxs, 16.0f);
    split2_kernel<<<MCODES / 2, 256>>>((const float4*)emb, (__half*)pes, 4096.0f);
    tcg256_kernel<3, 1, true><<<dim3(MCODES / 128, NROWS / 256), 256, SMEM>>>(
        (const uint16_t*)pxs, 1024, (const uint16_t*)pes, 1024, nullptr, 0);

    // --- VQ bookkeeping: counts -> scan -> ema -> scatter -> dw/emb ---
    countk_kernel<<<NROWS / 256, 256>>>();
    prefix_kernel<<<1, MCODES>>>();
    ema_kernel<<<1, MCODES>>>(ema_count, out_cnt, out_perp);
    scatter_kernel<<<NROWS / 256, 256>>>();
    dwsum_kernel<<<MCODES, 128>>>(x, ema_wt, out_emb, out_w);
    postvq_kernel<<<NROWS, 128>>>(x, emb, out_q);

    // --- decoder path: bf16 tensor-core GEMMs (4-stage pipeline) ---
    wconv_kernel<<<dim3(HDIM / 32, DDIM / 32), 256>>>(W1, (__nv_bfloat16*)pw1t, HDIM);
    wconv_kernel<<<dim3(MCODES / 32, HDIM / 32), 256>>>(W2, (__nv_bfloat16*)pw2t, MCODES);
    ln_relu_kernel<float><<<NROWS, 256>>>(x, ln1g, ln1b, (__nv_bfloat16*)pa1);
    tcg256_kernel<1, 3, false><<<dim3(HDIM / 128, NROWS / 256), 256, SMEM>>>(
        (const uint16_t*)pa1, 512, (const uint16_t*)pw1t, 512, (float*)phb, HDIM);
    ln_relu_kernel<__nv_bfloat16><<<NROWS, 256>>>((const __nv_bfloat16*)phb,
                                                  ln2g, ln2b, (__nv_bfloat16*)pa2);

    // --- W2 GEMM with fused CE partials, then combine ---
    detect_mask_kernel<<<1, 256>>>((const unsigned*)mask);
    detect_lab_kernel<<<1, 256>>>((const unsigned*)labels);
    labconv_kernel<<<NROWS / 256, 256>>>(labels);
    tcg256_kernel<1, 2, false><<<dim3(MCODES / 128, NROWS / 256), 256, SMEM>>>(
        (const uint16_t*)pa2, 512, (const uint16_t*)pw2t, 512, nullptr, 0);
    ce_combine_kernel<<<NROWS / 256, 256>>>(mask, out_loss);
}